// round 1
// baseline (speedup 1.0000x reference)
#include <cuda_runtime.h>
#include <math.h>

// Problem constants
#define B      4
#define LT     1024
#define LS     1024
#define DMODEL 1024
#define DFFN   4096
#define NHEAD  16
#define DKH    64
#define MROWS  (B * LT)   // 4096

// ---------------- scratch (static device allocations; no cudaMalloc) ----------
__device__ float g_ln [MROWS * DMODEL];
__device__ float g_q  [MROWS * DMODEL];
__device__ float g_k  [MROWS * DMODEL];
__device__ float g_v  [MROWS * DMODEL];
__device__ float g_ctx[MROWS * DMODEL];
__device__ float g_x  [MROWS * DMODEL];
__device__ float g_ffn[MROWS * DFFN];

// ---------------- LayerNorm: one block per row -------------------------------
__global__ void ln_kernel(const float* __restrict__ x,
                          const float* __restrict__ g,
                          const float* __restrict__ b,
                          float* __restrict__ y) {
    int row = blockIdx.x;
    const float4* xr = (const float4*)(x + (size_t)row * DMODEL);
    int tid = threadIdx.x;              // 256 threads, 4 floats each
    float4 xv = xr[tid];
    float s  = xv.x + xv.y + xv.z + xv.w;
    float ss = xv.x*xv.x + xv.y*xv.y + xv.z*xv.z + xv.w*xv.w;
    #pragma unroll
    for (int o = 16; o > 0; o >>= 1) {
        s  += __shfl_xor_sync(0xffffffffu, s, o);
        ss += __shfl_xor_sync(0xffffffffu, ss, o);
    }
    __shared__ float sh_s[8], sh_ss[8];
    int wid = tid >> 5, lane = tid & 31;
    if (lane == 0) { sh_s[wid] = s; sh_ss[wid] = ss; }
    __syncthreads();
    float ts = 0.f, tss = 0.f;
    #pragma unroll
    for (int w = 0; w < 8; w++) { ts += sh_s[w]; tss += sh_ss[w]; }
    float mean = ts * (1.0f / DMODEL);
    float var  = tss * (1.0f / DMODEL) - mean * mean;
    float rstd = rsqrtf(var + 1e-5f);
    float4 gv = ((const float4*)g)[tid];
    float4 bv = ((const float4*)b)[tid];
    float4 ov;
    ov.x = (xv.x - mean) * rstd * gv.x + bv.x;
    ov.y = (xv.y - mean) * rstd * gv.y + bv.y;
    ov.z = (xv.z - mean) * rstd * gv.z + bv.z;
    ov.w = (xv.w - mean) * rstd * gv.w + bv.w;
    ((float4*)(y + (size_t)row * DMODEL))[tid] = ov;
}

// ---------------- SGEMM: C = A[M,K] @ W[K,N] + bias (+gelu) (+residual) ------
// BM=BN=128, BK=8, 256 threads, 8x8 per thread. All dims divisible.
__device__ __forceinline__ float gelu_tanh(float t) {
    return 0.5f * t * (1.0f + tanhf(0.7978845608028654f * (t + 0.044715f * t * t * t)));
}

template<bool GELU, bool RES>
__global__ __launch_bounds__(256)
void sgemm(const float* __restrict__ A, const float* __restrict__ W,
           const float* __restrict__ bias, const float* __restrict__ res,
           float* __restrict__ C, int M, int N, int K) {
    __shared__ float As[8][128];
    __shared__ float Bs[8][128];
    int brow = blockIdx.y * 128;
    int bcol = blockIdx.x * 128;
    int tid = threadIdx.x;
    int tx = tid & 15, ty = tid >> 4;

    float acc[8][8] = {};
    int aRow = tid >> 1;            // 0..127
    int aCol = (tid & 1) * 4;       // 0 or 4
    int bRow = tid >> 5;            // 0..7
    int bCol = (tid & 31) * 4;      // 0..124

    const float* Aptr = A + (size_t)(brow + aRow) * K + aCol;
    for (int k0 = 0; k0 < K; k0 += 8) {
        float4 a4 = *(const float4*)(Aptr + k0);
        As[aCol + 0][aRow] = a4.x;
        As[aCol + 1][aRow] = a4.y;
        As[aCol + 2][aRow] = a4.z;
        As[aCol + 3][aRow] = a4.w;
        *(float4*)&Bs[bRow][bCol] =
            *(const float4*)&W[(size_t)(k0 + bRow) * N + bcol + bCol];
        __syncthreads();
        #pragma unroll
        for (int kk = 0; kk < 8; kk++) {
            float ra[8], rb[8];
            #pragma unroll
            for (int i = 0; i < 8; i++) ra[i] = As[kk][ty * 8 + i];
            #pragma unroll
            for (int j = 0; j < 8; j++) rb[j] = Bs[kk][tx * 8 + j];
            #pragma unroll
            for (int i = 0; i < 8; i++)
                #pragma unroll
                for (int j = 0; j < 8; j++)
                    acc[i][j] = fmaf(ra[i], rb[j], acc[i][j]);
        }
        __syncthreads();
    }

    #pragma unroll
    for (int i = 0; i < 8; i++) {
        int r = brow + ty * 8 + i;
        #pragma unroll
        for (int j = 0; j < 8; j += 4) {
            int c = bcol + tx * 8 + j;
            float4 o;
            float* po = &o.x;
            #pragma unroll
            for (int jj = 0; jj < 4; jj++) {
                float vv = acc[i][j + jj] + bias[c + jj];
                if (GELU) vv = gelu_tanh(vv);
                po[jj] = vv;
            }
            if (RES) {
                float4 rv = *(const float4*)&res[(size_t)r * N + c];
                o.x += rv.x; o.y += rv.y; o.z += rv.z; o.w += rv.w;
            }
            *(float4*)&C[(size_t)r * N + c] = o;
        }
    }
}

// ---------------- Fused attention (flash-style, fp32) -------------------------
// One block = (b,h) x 64-query tile. Layout: row = b*1024 + t, col = h*64 + d.
#define APAD 68
__global__ __launch_bounds__(256)
void attn_kernel(const float* __restrict__ Qb, const float* __restrict__ Kb,
                 const float* __restrict__ Vb, float* __restrict__ Ctx,
                 int causal, int nkt) {
    extern __shared__ float sm[];
    float* Qs   = sm;                    // [64][APAD]  q-major
    float* Kst  = Qs  + 64 * APAD;       // [64][APAD]  d-major (transposed)
    float* Vs   = Kst + 64 * APAD;       // [64][APAD]  k-major
    float* Ss   = Vs  + 64 * APAD;       // [64][APAD]
    float* mrow = Ss  + 64 * APAD;
    float* lrow = mrow + 64;
    float* arow = lrow + 64;

    int qt = blockIdx.x;
    int bh = blockIdx.y;
    int bb = bh / NHEAD, h = bh % NHEAD;
    int rowbase = bb * LT;
    int colbase = h * DKH;
    int tid = threadIdx.x;
    int tq = tid >> 4, tk = tid & 15;
    int q0 = tq * 4, d0 = tk * 4;

    // load Q tile, scaled by 1/sqrt(dk)
    {
        int lr = tid >> 2;
        int lc = (tid & 3) * 16;
        const float* src = Qb + (size_t)(rowbase + qt * 64 + lr) * DMODEL + colbase + lc;
        #pragma unroll
        for (int c = 0; c < 16; c += 4) {
            float4 v4 = *(const float4*)(src + c);
            float4 sv = make_float4(v4.x * 0.125f, v4.y * 0.125f, v4.z * 0.125f, v4.w * 0.125f);
            *(float4*)&Qs[lr * APAD + lc + c] = sv;
        }
    }
    if (tid < 64) { mrow[tid] = -1e30f; lrow[tid] = 0.f; }
    float O[4][4] = {};

    int ktmax = causal ? qt : (nkt - 1);
    for (int kt = 0; kt <= ktmax; kt++) {
        __syncthreads();   // previous-tile consumers done; Q load visible
        // load K (transposed) and V tiles
        {
            int lr = tid >> 2;
            int lc = (tid & 3) * 16;
            const float* ksrc = Kb + (size_t)(rowbase + kt * 64 + lr) * DMODEL + colbase + lc;
            const float* vsrc = Vb + (size_t)(rowbase + kt * 64 + lr) * DMODEL + colbase + lc;
            #pragma unroll
            for (int c = 0; c < 16; c += 4) {
                float4 k4 = *(const float4*)(ksrc + c);
                Kst[(lc + c + 0) * APAD + lr] = k4.x;
                Kst[(lc + c + 1) * APAD + lr] = k4.y;
                Kst[(lc + c + 2) * APAD + lr] = k4.z;
                Kst[(lc + c + 3) * APAD + lr] = k4.w;
                *(float4*)&Vs[lr * APAD + lc + c] = *(const float4*)(vsrc + c);
            }
        }
        __syncthreads();

        // scores S[4q][4k]
        float S[4][4] = {};
        #pragma unroll 4
        for (int d = 0; d < 64; d++) {
            float ra[4], rb[4];
            #pragma unroll
            for (int i = 0; i < 4; i++) ra[i] = Qs[(q0 + i) * APAD + d];
            #pragma unroll
            for (int j = 0; j < 4; j++) rb[j] = Kst[d * APAD + tk * 4 + j];
            #pragma unroll
            for (int i = 0; i < 4; i++)
                #pragma unroll
                for (int j = 0; j < 4; j++)
                    S[i][j] = fmaf(ra[i], rb[j], S[i][j]);
        }
        // mask + stage to smem
        #pragma unroll
        for (int i = 0; i < 4; i++) {
            int qg = qt * 64 + q0 + i;
            #pragma unroll
            for (int j = 0; j < 4; j++) {
                int kg = kt * 64 + tk * 4 + j;
                float s = S[i][j];
                if (causal && kg > qg) s = -1e30f;
                Ss[(q0 + i) * APAD + tk * 4 + j] = s;
            }
        }
        __syncthreads();

        // online softmax row stats (64 threads, one row each)
        if (tid < 64) {
            float* srow = &Ss[tid * APAD];
            float mn = mrow[tid];
            #pragma unroll 8
            for (int k = 0; k < 64; k++) mn = fmaxf(mn, srow[k]);
            float al = __expf(mrow[tid] - mn);
            float sum = 0.f;
            #pragma unroll 8
            for (int k = 0; k < 64; k++) {
                float p = __expf(srow[k] - mn);
                srow[k] = p;
                sum += p;
            }
            lrow[tid] = lrow[tid] * al + sum;
            mrow[tid] = mn;
            arow[tid] = al;
        }
        __syncthreads();

        // rescale + O += P @ V
        #pragma unroll
        for (int i = 0; i < 4; i++) {
            float a = arow[q0 + i];
            #pragma unroll
            for (int j = 0; j < 4; j++) O[i][j] *= a;
        }
        #pragma unroll 4
        for (int k = 0; k < 64; k++) {
            float p[4], vv[4];
            #pragma unroll
            for (int i = 0; i < 4; i++) p[i] = Ss[(q0 + i) * APAD + k];
            #pragma unroll
            for (int j = 0; j < 4; j++) vv[j] = Vs[k * APAD + d0 + j];
            #pragma unroll
            for (int i = 0; i < 4; i++)
                #pragma unroll
                for (int j = 0; j < 4; j++)
                    O[i][j] = fmaf(p[i], vv[j], O[i][j]);
        }
    }

    // finalize
    #pragma unroll
    for (int i = 0; i < 4; i++) {
        float inv = 1.0f / lrow[q0 + i];
        float4 o = make_float4(O[i][0] * inv, O[i][1] * inv, O[i][2] * inv, O[i][3] * inv);
        *(float4*)&Ctx[(size_t)(rowbase + qt * 64 + q0 + i) * DMODEL + colbase + d0] = o;
    }
}

// ---------------- driver -------------------------------------------------------
extern "C" void kernel_launch(void* const* d_in, const int* in_sizes, int n_in,
                              void* d_out, int out_size) {
    const float* tgt      = (const float*)d_in[0];
    const float* memory   = (const float*)d_in[1];
    // d_in[2] src_pad_mask (all false), d_in[3] tgt_mask (causal) -> analytic
    const float* self_wq  = (const float*)d_in[4];
    const float* self_bq  = (const float*)d_in[5];
    const float* self_wk  = (const float*)d_in[6];
    const float* self_bk  = (const float*)d_in[7];
    const float* self_wv  = (const float*)d_in[8];
    const float* self_bv  = (const float*)d_in[9];
    const float* self_wo  = (const float*)d_in[10];
    const float* self_bo  = (const float*)d_in[11];
    const float* cross_wq = (const float*)d_in[12];
    const float* cross_bq = (const float*)d_in[13];
    const float* cross_wk = (const float*)d_in[14];
    const float* cross_bk = (const float*)d_in[15];
    const float* cross_wv = (const float*)d_in[16];
    const float* cross_bv = (const float*)d_in[17];
    const float* cross_wo = (const float*)d_in[18];
    const float* cross_bo = (const float*)d_in[19];
    const float* ln1_g    = (const float*)d_in[20];
    const float* ln1_b    = (const float*)d_in[21];
    const float* ln2_g    = (const float*)d_in[22];
    const float* ln2_b    = (const float*)d_in[23];
    const float* ln3_g    = (const float*)d_in[24];
    const float* ln3_b    = (const float*)d_in[25];
    const float* ffn_w1   = (const float*)d_in[26];
    const float* ffn_b1   = (const float*)d_in[27];
    const float* ffn_w2   = (const float*)d_in[28];
    const float* ffn_b2   = (const float*)d_in[29];
    float* out = (float*)d_out;

    float *ln, *q, *k, *v, *ctx, *x, *ffn;
    cudaGetSymbolAddress((void**)&ln,  g_ln);
    cudaGetSymbolAddress((void**)&q,   g_q);
    cudaGetSymbolAddress((void**)&k,   g_k);
    cudaGetSymbolAddress((void**)&v,   g_v);
    cudaGetSymbolAddress((void**)&ctx, g_ctx);
    cudaGetSymbolAddress((void**)&x,   g_x);
    cudaGetSymbolAddress((void**)&ffn, g_ffn);

    const int attn_smem = (4 * 64 * APAD + 3 * 64) * (int)sizeof(float);
    cudaFuncSetAttribute(attn_kernel, cudaFuncAttributeMaxDynamicSharedMemorySize, attn_smem);

    dim3 blk(256);
    dim3 gD(DMODEL / 128, MROWS / 128);   // N=1024
    dim3 gF(DFFN / 128,   MROWS / 128);   // N=4096
    dim3 gA(LT / 64, B * NHEAD);

    // ---- sublayer 1: self-attention (pre-norm) ----
    ln_kernel<<<MROWS, blk>>>(tgt, ln1_g, ln1_b, ln);
    sgemm<false,false><<<gD, blk>>>(ln, self_wq, self_bq, nullptr, q,  MROWS, DMODEL, DMODEL);
    sgemm<false,false><<<gD, blk>>>(ln, self_wk, self_bk, nullptr, k,  MROWS, DMODEL, DMODEL);
    sgemm<false,false><<<gD, blk>>>(ln, self_wv, self_bv, nullptr, v,  MROWS, DMODEL, DMODEL);
    attn_kernel<<<gA, blk, attn_smem>>>(q, k, v, ctx, /*causal=*/1, LT / 64);
    sgemm<false,true ><<<gD, blk>>>(ctx, self_wo, self_bo, tgt, x, MROWS, DMODEL, DMODEL);

    // ---- sublayer 2: cross-attention ----
    ln_kernel<<<MROWS, blk>>>(x, ln2_g, ln2_b, ln);
    sgemm<false,false><<<gD, blk>>>(ln,     cross_wq, cross_bq, nullptr, q, MROWS, DMODEL, DMODEL);
    sgemm<false,false><<<gD, blk>>>(memory, cross_wk, cross_bk, nullptr, k, MROWS, DMODEL, DMODEL);
    sgemm<false,false><<<gD, blk>>>(memory, cross_wv, cross_bv, nullptr, v, MROWS, DMODEL, DMODEL);
    attn_kernel<<<gA, blk, attn_smem>>>(q, k, v, ctx, /*causal=*/0, LS / 64);
    sgemm<false,true ><<<gD, blk>>>(ctx, cross_wo, cross_bo, x, x, MROWS, DMODEL, DMODEL);

    // ---- sublayer 3: FFN ----
    ln_kernel<<<MROWS, blk>>>(x, ln3_g, ln3_b, ln);
    sgemm<true ,false><<<gF, blk>>>(ln,  ffn_w1, ffn_b1, nullptr, ffn, MROWS, DFFN,   DMODEL);
    sgemm<false,true ><<<gD, blk>>>(ffn, ffn_w2, ffn_b2, x, out, MROWS, DMODEL, DFFN);
}

// round 3
// speedup vs baseline: 1.2689x; 1.2689x over previous
#include <cuda_runtime.h>
#include <cstdint>
#include <math.h>

// Problem constants
#define B      4
#define LT     1024
#define LS     1024
#define DMODEL 1024
#define DFFN   4096
#define NHEAD  16
#define DKH    64
#define MROWS  (B * LT)   // 4096

// ---------------- scratch (static device allocations; no cudaMalloc) ----------
__device__ float g_ln [MROWS * DMODEL];
__device__ float g_q  [MROWS * DMODEL];
__device__ float g_k  [MROWS * DMODEL];
__device__ float g_v  [MROWS * DMODEL];
__device__ float g_ctx[MROWS * DMODEL];
__device__ float g_x  [MROWS * DMODEL];
__device__ float g_ffn[MROWS * DFFN];
__device__ float g_wt [16 * 1024 * 1024];   // transposed weights, 64MB

// ---------------- LayerNorm: one block per row -------------------------------
__global__ void ln_kernel(const float* __restrict__ x,
                          const float* __restrict__ g,
                          const float* __restrict__ b,
                          float* __restrict__ y) {
    int row = blockIdx.x;
    const float4* xr = (const float4*)(x + (size_t)row * DMODEL);
    int tid = threadIdx.x;              // 256 threads, 4 floats each
    float4 xv = xr[tid];
    float s  = xv.x + xv.y + xv.z + xv.w;
    float ss = xv.x*xv.x + xv.y*xv.y + xv.z*xv.z + xv.w*xv.w;
    #pragma unroll
    for (int o = 16; o > 0; o >>= 1) {
        s  += __shfl_xor_sync(0xffffffffu, s, o);
        ss += __shfl_xor_sync(0xffffffffu, ss, o);
    }
    __shared__ float sh_s[8], sh_ss[8];
    int wid = tid >> 5, lane = tid & 31;
    if (lane == 0) { sh_s[wid] = s; sh_ss[wid] = ss; }
    __syncthreads();
    float ts = 0.f, tss = 0.f;
    #pragma unroll
    for (int w = 0; w < 8; w++) { ts += sh_s[w]; tss += sh_ss[w]; }
    float mean = ts * (1.0f / DMODEL);
    float var  = tss * (1.0f / DMODEL) - mean * mean;
    float rstd = rsqrtf(var + 1e-5f);
    float4 gv = ((const float4*)g)[tid];
    float4 bv = ((const float4*)b)[tid];
    float4 ov;
    ov.x = (xv.x - mean) * rstd * gv.x + bv.x;
    ov.y = (xv.y - mean) * rstd * gv.y + bv.y;
    ov.z = (xv.z - mean) * rstd * gv.z + bv.z;
    ov.w = (xv.w - mean) * rstd * gv.w + bv.w;
    ((float4*)(y + (size_t)row * DMODEL))[tid] = ov;
}

// ---------------- weight transpose: Wt[n][k] = W[k][n] -----------------------
__global__ void transpose_k(const float* __restrict__ W, float* __restrict__ Wt,
                            int K, int N) {
    __shared__ float t[32][33];
    int n0 = blockIdx.x * 32, k0 = blockIdx.y * 32;
    int tx = threadIdx.x, ty = threadIdx.y;
    #pragma unroll
    for (int i = ty; i < 32; i += 8)
        t[i][tx] = W[(size_t)(k0 + i) * N + n0 + tx];
    __syncthreads();
    #pragma unroll
    for (int i = ty; i < 32; i += 8)
        Wt[(size_t)(n0 + i) * K + k0 + tx] = t[tx][i];
}

// ---------------- tf32 mma.sync GEMM -----------------------------------------
// C[M,N] = A[M,K] @ Bt[N,K]^T (+bias) (+gelu) (+residual)
// BM=BN=128, BK=32. 256 threads = 8 warps; warp tile 64x32 (4x4 m16n8k8).
#define BM 128
#define BN 128
#define BK 32
#define SKA 36   // padded row stride (floats)

__device__ __forceinline__ float gelu_tanh(float t) {
    return 0.5f * t * (1.0f + tanhf(0.7978845608028654f * (t + 0.044715f * t * t * t)));
}

__device__ __forceinline__ void mma_tf32_16x8x8(float c[4], const uint32_t a[4],
                                                const uint32_t b[2]) {
    asm volatile(
        "mma.sync.aligned.m16n8k8.row.col.f32.tf32.tf32.f32 "
        "{%0,%1,%2,%3}, {%4,%5,%6,%7}, {%8,%9}, {%0,%1,%2,%3};"
        : "+f"(c[0]), "+f"(c[1]), "+f"(c[2]), "+f"(c[3])
        : "r"(a[0]), "r"(a[1]), "r"(a[2]), "r"(a[3]), "r"(b[0]), "r"(b[1]));
}
__device__ __forceinline__ uint32_t to_tf32(float f) {
    uint32_t u;
    asm volatile("cvt.rna.tf32.f32 %0, %1;" : "=r"(u) : "f"(f));
    return u;
}

template<bool GELU, bool RES>
__global__ __launch_bounds__(256)
void tcgemm(const float* __restrict__ A, const float* __restrict__ Bt,
            const float* __restrict__ bias, const float* __restrict__ res,
            float* __restrict__ C, int M, int N, int K) {
    __shared__ uint32_t As[2][BM * SKA];
    __shared__ uint32_t Bs[2][BN * SKA];

    int tid  = threadIdx.x;
    int wid  = tid >> 5;
    int lane = tid & 31;
    int g = lane >> 2, q = lane & 3;
    int wr = wid >> 2;           // 0..1 -> m offset 64*wr
    int wc = wid & 3;            // 0..3 -> n offset 32*wc
    int rbase = wr * 64;
    int nbase = wc * 32;

    int brow = blockIdx.y * BM;
    int bcol = blockIdx.x * BN;
    const int NKB = K / BK;

    // loader indices: 1024 float4 per tile, 4 per thread
    int lr  = tid >> 1;                 // unused pattern replaced below
    (void)lr;

    float4 ra[4], rbv[4];
    const float* Abase = A  + (size_t)brow * K;
    const float* Bbase = Bt + (size_t)bcol * K;

    auto ldg_chunk = [&](int kb) {
        #pragma unroll
        for (int i = 0; i < 4; i++) {
            int f = tid + 256 * i;       // 0..1023
            int r = f >> 3;
            int c4 = (f & 7) << 2;
            ra[i]  = *(const float4*)(Abase + (size_t)r * K + kb * BK + c4);
            rbv[i] = *(const float4*)(Bbase + (size_t)r * K + kb * BK + c4);
        }
    };
    auto sts_chunk = [&](int s) {
        #pragma unroll
        for (int i = 0; i < 4; i++) {
            int f = tid + 256 * i;
            int r = f >> 3;
            int c4 = (f & 7) << 2;
            uint32_t* pa = &As[s][r * SKA + c4];
            pa[0] = to_tf32(ra[i].x); pa[1] = to_tf32(ra[i].y);
            pa[2] = to_tf32(ra[i].z); pa[3] = to_tf32(ra[i].w);
            uint32_t* pb = &Bs[s][r * SKA + c4];
            pb[0] = to_tf32(rbv[i].x); pb[1] = to_tf32(rbv[i].y);
            pb[2] = to_tf32(rbv[i].z); pb[3] = to_tf32(rbv[i].w);
        }
    };

    float acc[4][4][4] = {};

    ldg_chunk(0);
    sts_chunk(0);
    __syncthreads();

    for (int kb = 0; kb < NKB; kb++) {
        int s = kb & 1;
        if (kb + 1 < NKB) ldg_chunk(kb + 1);

        const uint32_t* Asb = &As[s][0];
        const uint32_t* Bsb = &Bs[s][0];
        #pragma unroll
        for (int kk = 0; kk < BK; kk += 8) {
            uint32_t af[4][4];
            #pragma unroll
            for (int tm = 0; tm < 4; tm++) {
                int r0 = (rbase + tm * 16 + g) * SKA + kk + q;
                af[tm][0] = Asb[r0];
                af[tm][1] = Asb[r0 + 8 * SKA];
                af[tm][2] = Asb[r0 + 4];
                af[tm][3] = Asb[r0 + 8 * SKA + 4];
            }
            uint32_t bf[4][2];
            #pragma unroll
            for (int tn = 0; tn < 4; tn++) {
                int n0 = (nbase + tn * 8 + g) * SKA + kk + q;
                bf[tn][0] = Bsb[n0];
                bf[tn][1] = Bsb[n0 + 4];
            }
            #pragma unroll
            for (int tm = 0; tm < 4; tm++)
                #pragma unroll
                for (int tn = 0; tn < 4; tn++)
                    mma_tf32_16x8x8(acc[tm][tn], af[tm], bf[tn]);
        }

        if (kb + 1 < NKB) {
            sts_chunk(s ^ 1);
            __syncthreads();
        }
    }

    // ---- epilogue ----
    #pragma unroll
    for (int tm = 0; tm < 4; tm++) {
        #pragma unroll
        for (int half = 0; half < 2; half++) {
            int r = brow + rbase + tm * 16 + g + half * 8;
            float* Crow = C + (size_t)r * N;
            const float* Rrow = RES ? (res + (size_t)r * N) : nullptr;
            #pragma unroll
            for (int tn = 0; tn < 4; tn++) {
                int c = bcol + nbase + tn * 8 + q * 2;
                float o0 = acc[tm][tn][half * 2 + 0] + bias[c];
                float o1 = acc[tm][tn][half * 2 + 1] + bias[c + 1];
                if (GELU) { o0 = gelu_tanh(o0); o1 = gelu_tanh(o1); }
                if (RES) {
                    float2 rv = *(const float2*)(Rrow + c);
                    o0 += rv.x; o1 += rv.y;
                }
                *(float2*)(Crow + c) = make_float2(o0, o1);
            }
        }
    }
}

// ---------------- Fused attention (flash-style, fp32) -------------------------
#define APAD 68
__global__ __launch_bounds__(256)
void attn_kernel(const float* __restrict__ Qb, const float* __restrict__ Kb,
                 const float* __restrict__ Vb, float* __restrict__ Ctx,
                 int causal, int nkt) {
    extern __shared__ float sm[];
    float* Qs   = sm;                    // [64][APAD]  q-major
    float* Kst  = Qs  + 64 * APAD;       // [64][APAD]  d-major (transposed)
    float* Vs   = Kst + 64 * APAD;       // [64][APAD]  k-major
    float* Ss   = Vs  + 64 * APAD;       // [64][APAD]
    float* mrow = Ss  + 64 * APAD;
    float* lrow = mrow + 64;
    float* arow = lrow + 64;

    int qt = blockIdx.x;
    int bh = blockIdx.y;
    int bb = bh / NHEAD, h = bh % NHEAD;
    int rowbase = bb * LT;
    int colbase = h * DKH;
    int tid = threadIdx.x;
    int tq = tid >> 4, tk = tid & 15;
    int q0 = tq * 4, d0 = tk * 4;

    {
        int lr = tid >> 2;
        int lc = (tid & 3) * 16;
        const float* src = Qb + (size_t)(rowbase + qt * 64 + lr) * DMODEL + colbase + lc;
        #pragma unroll
        for (int c = 0; c < 16; c += 4) {
            float4 v4 = *(const float4*)(src + c);
            float4 sv = make_float4(v4.x * 0.125f, v4.y * 0.125f, v4.z * 0.125f, v4.w * 0.125f);
            *(float4*)&Qs[lr * APAD + lc + c] = sv;
        }
    }
    if (tid < 64) { mrow[tid] = -1e30f; lrow[tid] = 0.f; }
    float O[4][4] = {};

    int ktmax = causal ? qt : (nkt - 1);
    for (int kt = 0; kt <= ktmax; kt++) {
        __syncthreads();
        {
            int lr = tid >> 2;
            int lc = (tid & 3) * 16;
            const float* ksrc = Kb + (size_t)(rowbase + kt * 64 + lr) * DMODEL + colbase + lc;
            const float* vsrc = Vb + (size_t)(rowbase + kt * 64 + lr) * DMODEL + colbase + lc;
            #pragma unroll
            for (int c = 0; c < 16; c += 4) {
                float4 k4 = *(const float4*)(ksrc + c);
                Kst[(lc + c + 0) * APAD + lr] = k4.x;
                Kst[(lc + c + 1) * APAD + lr] = k4.y;
                Kst[(lc + c + 2) * APAD + lr] = k4.z;
                Kst[(lc + c + 3) * APAD + lr] = k4.w;
                *(float4*)&Vs[lr * APAD + lc + c] = *(const float4*)(vsrc + c);
            }
        }
        __syncthreads();

        float S[4][4] = {};
        #pragma unroll 4
        for (int d = 0; d < 64; d++) {
            float ra4[4], rb4[4];
            #pragma unroll
            for (int i = 0; i < 4; i++) ra4[i] = Qs[(q0 + i) * APAD + d];
            #pragma unroll
            for (int j = 0; j < 4; j++) rb4[j] = Kst[d * APAD + tk * 4 + j];
            #pragma unroll
            for (int i = 0; i < 4; i++)
                #pragma unroll
                for (int j = 0; j < 4; j++)
                    S[i][j] = fmaf(ra4[i], rb4[j], S[i][j]);
        }
        #pragma unroll
        for (int i = 0; i < 4; i++) {
            int qg = qt * 64 + q0 + i;
            #pragma unroll
            for (int j = 0; j < 4; j++) {
                int kg = kt * 64 + tk * 4 + j;
                float s = S[i][j];
                if (causal && kg > qg) s = -1e30f;
                Ss[(q0 + i) * APAD + tk * 4 + j] = s;
            }
        }
        __syncthreads();

        if (tid < 64) {
            float* srow = &Ss[tid * APAD];
            float mn = mrow[tid];
            #pragma unroll 8
            for (int k = 0; k < 64; k++) mn = fmaxf(mn, srow[k]);
            float al = __expf(mrow[tid] - mn);
            float sum = 0.f;
            #pragma unroll 8
            for (int k = 0; k < 64; k++) {
                float p = __expf(srow[k] - mn);
                srow[k] = p;
                sum += p;
            }
            lrow[tid] = lrow[tid] * al + sum;
            mrow[tid] = mn;
            arow[tid] = al;
        }
        __syncthreads();

        #pragma unroll
        for (int i = 0; i < 4; i++) {
            float a = arow[q0 + i];
            #pragma unroll
            for (int j = 0; j < 4; j++) O[i][j] *= a;
        }
        #pragma unroll 4
        for (int k = 0; k < 64; k++) {
            float p[4], vv[4];
            #pragma unroll
            for (int i = 0; i < 4; i++) p[i] = Ss[(q0 + i) * APAD + k];
            #pragma unroll
            for (int j = 0; j < 4; j++) vv[j] = Vs[k * APAD + d0 + j];
            #pragma unroll
            for (int i = 0; i < 4; i++)
                #pragma unroll
                for (int j = 0; j < 4; j++)
                    O[i][j] = fmaf(p[i], vv[j], O[i][j]);
        }
    }

    #pragma unroll
    for (int i = 0; i < 4; i++) {
        float inv = 1.0f / lrow[q0 + i];
        float4 o = make_float4(O[i][0] * inv, O[i][1] * inv, O[i][2] * inv, O[i][3] * inv);
        *(float4*)&Ctx[(size_t)(rowbase + qt * 64 + q0 + i) * DMODEL + colbase + d0] = o;
    }
}

// ---------------- driver -------------------------------------------------------
extern "C" void kernel_launch(void* const* d_in, const int* in_sizes, int n_in,
                              void* d_out, int out_size) {
    const float* tgt      = (const float*)d_in[0];
    const float* memory   = (const float*)d_in[1];
    const float* self_wq  = (const float*)d_in[4];
    const float* self_bq  = (const float*)d_in[5];
    const float* self_wk  = (const float*)d_in[6];
    const float* self_bk  = (const float*)d_in[7];
    const float* self_wv  = (const float*)d_in[8];
    const float* self_bv  = (const float*)d_in[9];
    const float* self_wo  = (const float*)d_in[10];
    const float* self_bo  = (const float*)d_in[11];
    const float* cross_wq = (const float*)d_in[12];
    const float* cross_bq = (const float*)d_in[13];
    const float* cross_wk = (const float*)d_in[14];
    const float* cross_bk = (const float*)d_in[15];
    const float* cross_wv = (const float*)d_in[16];
    const float* cross_bv = (const float*)d_in[17];
    const float* cross_wo = (const float*)d_in[18];
    const float* cross_bo = (const float*)d_in[19];
    const float* ln1_g    = (const float*)d_in[20];
    const float* ln1_b    = (const float*)d_in[21];
    const float* ln2_g    = (const float*)d_in[22];
    const float* ln2_b    = (const float*)d_in[23];
    const float* ln3_g    = (const float*)d_in[24];
    const float* ln3_b    = (const float*)d_in[25];
    const float* ffn_w1   = (const float*)d_in[26];
    const float* ffn_b1   = (const float*)d_in[27];
    const float* ffn_w2   = (const float*)d_in[28];
    const float* ffn_b2   = (const float*)d_in[29];
    float* out = (float*)d_out;

    float *ln, *q, *k, *v, *ctx, *x, *ffn, *wt;
    cudaGetSymbolAddress((void**)&ln,  g_ln);
    cudaGetSymbolAddress((void**)&q,   g_q);
    cudaGetSymbolAddress((void**)&k,   g_k);
    cudaGetSymbolAddress((void**)&v,   g_v);
    cudaGetSymbolAddress((void**)&ctx, g_ctx);
    cudaGetSymbolAddress((void**)&x,   g_x);
    cudaGetSymbolAddress((void**)&ffn, g_ffn);
    cudaGetSymbolAddress((void**)&wt,  g_wt);

    const int M1 = 1024 * 1024;
    float* t_swq = wt + 0 * M1;
    float* t_swk = wt + 1 * M1;
    float* t_swv = wt + 2 * M1;
    float* t_swo = wt + 3 * M1;
    float* t_cwq = wt + 4 * M1;
    float* t_cwk = wt + 5 * M1;
    float* t_cwv = wt + 6 * M1;
    float* t_cwo = wt + 7 * M1;
    float* t_w1  = wt + 8 * M1;    // [DFFN, DMODEL]
    float* t_w2  = wt + 12 * M1;   // [DMODEL, DFFN]

    const int attn_smem = (4 * 64 * APAD + 3 * 64) * (int)sizeof(float);
    cudaFuncSetAttribute(attn_kernel, cudaFuncAttributeMaxDynamicSharedMemorySize, attn_smem);

    dim3 blk(256);
    dim3 tb(32, 8);

    // ---- weight transposes (Wt[n][k] = W[k][n]) ----
    transpose_k<<<dim3(32, 32),  tb>>>(self_wq,  t_swq, DMODEL, DMODEL);
    transpose_k<<<dim3(32, 32),  tb>>>(self_wk,  t_swk, DMODEL, DMODEL);
    transpose_k<<<dim3(32, 32),  tb>>>(self_wv,  t_swv, DMODEL, DMODEL);
    transpose_k<<<dim3(32, 32),  tb>>>(self_wo,  t_swo, DMODEL, DMODEL);
    transpose_k<<<dim3(32, 32),  tb>>>(cross_wq, t_cwq, DMODEL, DMODEL);
    transpose_k<<<dim3(32, 32),  tb>>>(cross_wk, t_cwk, DMODEL, DMODEL);
    transpose_k<<<dim3(32, 32),  tb>>>(cross_wv, t_cwv, DMODEL, DMODEL);
    transpose_k<<<dim3(32, 32),  tb>>>(cross_wo, t_cwo, DMODEL, DMODEL);
    transpose_k<<<dim3(128, 32), tb>>>(ffn_w1,   t_w1,  DMODEL, DFFN);
    transpose_k<<<dim3(32, 128), tb>>>(ffn_w2,   t_w2,  DFFN,   DMODEL);

    dim3 gD(DMODEL / BN, MROWS / BM);   // (8, 32)
    dim3 gF(DFFN / BN,   MROWS / BM);   // (32, 32)
    dim3 gA(LT / 64, B * NHEAD);

    // ---- sublayer 1: self-attention (pre-norm) ----
    ln_kernel<<<MROWS, blk>>>(tgt, ln1_g, ln1_b, ln);
    tcgemm<false, false><<<gD, blk>>>(ln, t_swq, self_bq, nullptr, q, MROWS, DMODEL, DMODEL);
    tcgemm<false, false><<<gD, blk>>>(ln, t_swk, self_bk, nullptr, k, MROWS, DMODEL, DMODEL);
    tcgemm<false, false><<<gD, blk>>>(ln, t_swv, self_bv, nullptr, v, MROWS, DMODEL, DMODEL);
    attn_kernel<<<gA, blk, attn_smem>>>(q, k, v, ctx, /*causal=*/1, LT / 64);
    tcgemm<false, true ><<<gD, blk>>>(ctx, t_swo, self_bo, tgt, x, MROWS, DMODEL, DMODEL);

    // ---- sublayer 2: cross-attention ----
    ln_kernel<<<MROWS, blk>>>(x, ln2_g, ln2_b, ln);
    tcgemm<false, false><<<gD, blk>>>(ln,     t_cwq, cross_bq, nullptr, q, MROWS, DMODEL, DMODEL);
    tcgemm<false, false><<<gD, blk>>>(memory, t_cwk, cross_bk, nullptr, k, MROWS, DMODEL, DMODEL);
    tcgemm<false, false><<<gD, blk>>>(memory, t_cwv, cross_bv, nullptr, v, MROWS, DMODEL, DMODEL);
    attn_kernel<<<gA, blk, attn_smem>>>(q, k, v, ctx, /*causal=*/0, LS / 64);
    tcgemm<false, true ><<<gD, blk>>>(ctx, t_cwo, cross_bo, x, x, MROWS, DMODEL, DMODEL);

    // ---- sublayer 3: FFN ----
    ln_kernel<<<MROWS, blk>>>(x, ln3_g, ln3_b, ln);
    tcgemm<true,  false><<<gF, blk>>>(ln,  t_w1, ffn_b1, nullptr, ffn, MROWS, DFFN,   DMODEL);
    tcgemm<false, true ><<<gD, blk>>>(ffn, t_w2, ffn_b2, x, out, MROWS, DMODEL, DFFN);
}

// round 4
// speedup vs baseline: 5.2770x; 4.1587x over previous
#include <cuda_runtime.h>
#include <cuda_fp16.h>
#include <cstdint>
#include <math.h>

// Problem constants
#define B      4
#define LT     1024
#define LS     1024
#define DMODEL 1024
#define DFFN   4096
#define NHEAD  16
#define DKH    64
#define MROWS  (B * LT)   // 4096

// ---------------- scratch (static device allocations; no cudaMalloc) ----------
__device__ __half g_ln [MROWS * DMODEL];
__device__ __half g_q  [MROWS * DMODEL];
__device__ __half g_k  [MROWS * DMODEL];
__device__ __half g_v  [MROWS * DMODEL];
__device__ __half g_ctx[MROWS * DMODEL];
__device__ float  g_x  [MROWS * DMODEL];
__device__ __half g_ffn[(size_t)MROWS * DFFN];
__device__ __half g_wh [16u * 1024u * 1024u];   // transposed fp16 weights, 32MB

// ---------------- helpers ------------------------------------------------------
__device__ __forceinline__ uint32_t packh2(float a, float b) {
    __half2 h = __floats2half2_rn(a, b);
    return *(uint32_t*)&h;
}
__device__ __forceinline__ void mma_f16(float c[4], const uint32_t a[4], const uint32_t b[2]) {
    asm volatile(
        "mma.sync.aligned.m16n8k16.row.col.f32.f16.f16.f32 "
        "{%0,%1,%2,%3}, {%4,%5,%6,%7}, {%8,%9}, {%0,%1,%2,%3};"
        : "+f"(c[0]), "+f"(c[1]), "+f"(c[2]), "+f"(c[3])
        : "r"(a[0]), "r"(a[1]), "r"(a[2]), "r"(a[3]), "r"(b[0]), "r"(b[1]));
}
__device__ __forceinline__ float gelu_tanh(float t) {
    return 0.5f * t * (1.0f + tanhf(0.7978845608028654f * (t + 0.044715f * t * t * t)));
}

// ---------------- LayerNorm: fp32 in, fp16 out --------------------------------
__global__ void ln_kernel(const float* __restrict__ x,
                          const float* __restrict__ g,
                          const float* __restrict__ b,
                          __half* __restrict__ y) {
    int row = blockIdx.x;
    const float4* xr = (const float4*)(x + (size_t)row * DMODEL);
    int tid = threadIdx.x;              // 256 threads, 4 floats each
    float4 xv = xr[tid];
    float s  = xv.x + xv.y + xv.z + xv.w;
    float ss = xv.x*xv.x + xv.y*xv.y + xv.z*xv.z + xv.w*xv.w;
    #pragma unroll
    for (int o = 16; o > 0; o >>= 1) {
        s  += __shfl_xor_sync(0xffffffffu, s, o);
        ss += __shfl_xor_sync(0xffffffffu, ss, o);
    }
    __shared__ float sh_s[8], sh_ss[8];
    int wid = tid >> 5, lane = tid & 31;
    if (lane == 0) { sh_s[wid] = s; sh_ss[wid] = ss; }
    __syncthreads();
    float ts = 0.f, tss = 0.f;
    #pragma unroll
    for (int w = 0; w < 8; w++) { ts += sh_s[w]; tss += sh_ss[w]; }
    float mean = ts * (1.0f / DMODEL);
    float var  = tss * (1.0f / DMODEL) - mean * mean;
    float rstd = rsqrtf(var + 1e-5f);
    float4 gv = ((const float4*)g)[tid];
    float4 bv = ((const float4*)b)[tid];
    uint2 o;
    o.x = packh2((xv.x - mean) * rstd * gv.x + bv.x, (xv.y - mean) * rstd * gv.y + bv.y);
    o.y = packh2((xv.z - mean) * rstd * gv.z + bv.z, (xv.w - mean) * rstd * gv.w + bv.w);
    ((uint2*)(y + (size_t)row * DMODEL))[tid] = o;
}

// ---------------- weight transpose+convert: Wt[n][k] = half(W[k][n]) ---------
__global__ void transpose_cvt(const float* __restrict__ W, __half* __restrict__ Wt,
                              int K, int N) {
    __shared__ float t[32][33];
    int n0 = blockIdx.x * 32, k0 = blockIdx.y * 32;
    int tx = threadIdx.x, ty = threadIdx.y;
    #pragma unroll
    for (int i = ty; i < 32; i += 8)
        t[i][tx] = W[(size_t)(k0 + i) * N + n0 + tx];
    __syncthreads();
    #pragma unroll
    for (int i = ty; i < 32; i += 8)
        Wt[(size_t)(n0 + i) * K + k0 + tx] = __float2half(t[tx][i]);
}

// ---------------- fp16 mma GEMM ----------------------------------------------
// C[M,N] = A[M,K](half) @ Bt[N,K](half)^T (+bias) (+gelu) (+residual fp32)
// BM=BN=128, BK=32. 256 threads = 8 warps; warp tile 64x32 (4x4 of m16n8k16).
#define BM 128
#define BN 128
#define BK 32
#define SKH 40   // padded row stride in halfs (20 words -> conflict-free frag LDS)

template<bool OUT_HALF, bool GELU, bool RES>
__global__ __launch_bounds__(256)
void hgemm(const __half* __restrict__ A, const __half* __restrict__ Bt,
           const float* __restrict__ bias, const float* __restrict__ res,
           void* __restrict__ Cout, int M, int N, int K) {
    __shared__ alignas(16) __half As[2][BM * SKH];
    __shared__ alignas(16) __half Bs[2][BN * SKH];

    int tid  = threadIdx.x;
    int wid  = tid >> 5;
    int lane = tid & 31;
    int g = lane >> 2, q = lane & 3;
    int rbase = (wid >> 2) * 64;   // warp m offset
    int nbase = (wid & 3) * 32;    // warp n offset

    int brow = blockIdx.y * BM;
    int bcol = blockIdx.x * BN;
    const int NKB = K / BK;

    const __half* Abase = A  + (size_t)brow * K;
    const __half* Bbase = Bt + (size_t)bcol * K;

    uint4 ra[2], rb[2];
    auto ldg_chunk = [&](int kb) {
        #pragma unroll
        for (int i = 0; i < 2; i++) {
            int f = tid + 256 * i;           // 0..511
            int r = f >> 2;
            int c8 = (f & 3) * 8;
            ra[i] = *(const uint4*)(Abase + (size_t)r * K + kb * BK + c8);
            rb[i] = *(const uint4*)(Bbase + (size_t)r * K + kb * BK + c8);
        }
    };
    auto sts_chunk = [&](int s) {
        #pragma unroll
        for (int i = 0; i < 2; i++) {
            int f = tid + 256 * i;
            int r = f >> 2;
            int c8 = (f & 3) * 8;
            *(uint4*)&As[s][r * SKH + c8] = ra[i];
            *(uint4*)&Bs[s][r * SKH + c8] = rb[i];
        }
    };

    float acc[4][4][4] = {};

    ldg_chunk(0);
    sts_chunk(0);
    __syncthreads();

    for (int kb = 0; kb < NKB; kb++) {
        int s = kb & 1;
        if (kb + 1 < NKB) ldg_chunk(kb + 1);

        const __half* Asb = &As[s][0];
        const __half* Bsb = &Bs[s][0];
        #pragma unroll
        for (int kk = 0; kk < BK; kk += 16) {
            uint32_t af[4][4];
            #pragma unroll
            for (int tm = 0; tm < 4; tm++) {
                int r0 = (rbase + tm * 16 + g) * SKH + kk + q * 2;
                af[tm][0] = *(const uint32_t*)&Asb[r0];
                af[tm][1] = *(const uint32_t*)&Asb[r0 + 8 * SKH];
                af[tm][2] = *(const uint32_t*)&Asb[r0 + 8];
                af[tm][3] = *(const uint32_t*)&Asb[r0 + 8 * SKH + 8];
            }
            uint32_t bf[4][2];
            #pragma unroll
            for (int tn = 0; tn < 4; tn++) {
                int n0 = (nbase + tn * 8 + g) * SKH + kk + q * 2;
                bf[tn][0] = *(const uint32_t*)&Bsb[n0];
                bf[tn][1] = *(const uint32_t*)&Bsb[n0 + 8];
            }
            #pragma unroll
            for (int tm = 0; tm < 4; tm++)
                #pragma unroll
                for (int tn = 0; tn < 4; tn++)
                    mma_f16(acc[tm][tn], af[tm], bf[tn]);
        }

        if (kb + 1 < NKB) {
            sts_chunk(s ^ 1);
            __syncthreads();
        }
    }

    // ---- epilogue ----
    #pragma unroll
    for (int tm = 0; tm < 4; tm++) {
        #pragma unroll
        for (int half_i = 0; half_i < 2; half_i++) {
            int r = brow + rbase + tm * 16 + g + half_i * 8;
            #pragma unroll
            for (int tn = 0; tn < 4; tn++) {
                int c = bcol + nbase + tn * 8 + q * 2;
                float o0 = acc[tm][tn][half_i * 2 + 0] + bias[c];
                float o1 = acc[tm][tn][half_i * 2 + 1] + bias[c + 1];
                if (GELU) { o0 = gelu_tanh(o0); o1 = gelu_tanh(o1); }
                if (RES) {
                    float2 rv = *(const float2*)(res + (size_t)r * N + c);
                    o0 += rv.x; o1 += rv.y;
                }
                if (OUT_HALF) {
                    uint32_t p = packh2(o0, o1);
                    *(uint32_t*)((__half*)Cout + (size_t)r * N + c) = p;
                } else {
                    *(float2*)((float*)Cout + (size_t)r * N + c) = make_float2(o0, o1);
                }
            }
        }
    }
}

// ---------------- fp16 tensor-core flash attention ----------------------------
// Block: 128 threads (4 warps); warp handles 16 query rows of a 64-row q-tile.
// K/V tiles of 64 keys in smem. Online softmax in fp32 fragments.
#define ATS 72   // padded smem row stride in halfs
__global__ __launch_bounds__(128)
void attn_kernel(const __half* __restrict__ Qb, const __half* __restrict__ Kb,
                 const __half* __restrict__ Vb, __half* __restrict__ Ctx,
                 int causal, int nkt) {
    __shared__ alignas(16) __half Qs[64 * ATS];
    __shared__ alignas(16) __half Ks[64 * ATS];
    __shared__ alignas(16) __half Vs[64 * ATS];

    int qt = blockIdx.x;
    int bh = blockIdx.y;
    int bb = bh >> 4, h = bh & 15;
    int rowbase = bb * LT;
    int colbase = h * DKH;
    int tid = threadIdx.x;
    int w = tid >> 5, lane = tid & 31;
    int g = lane >> 2, q = lane & 3;

    // load Q tile (scaled by 1/sqrt(dk)=0.125)
    {
        const __half2 sc = __floats2half2_rn(0.125f, 0.125f);
        #pragma unroll
        for (int i = 0; i < 4; i++) {
            int f = tid + 128 * i;
            int lr = f >> 3;
            int c8 = (f & 7) * 8;
            const __half2* src = (const __half2*)(Qb + (size_t)(rowbase + qt * 64 + lr) * DMODEL + colbase + c8);
            __half2 vv[4];
            #pragma unroll
            for (int j = 0; j < 4; j++) vv[j] = __hmul2(src[j], sc);
            *(float4*)&Qs[lr * ATS + c8] = *(float4*)vv;
        }
    }
    __syncthreads();

    // Q fragments (persist in registers)
    uint32_t qfr[4][4];
    {
        int r0 = (w * 16 + g) * ATS;
        #pragma unroll
        for (int jk = 0; jk < 4; jk++) {
            int kk = jk * 16;
            qfr[jk][0] = *(const uint32_t*)&Qs[r0 + kk + q * 2];
            qfr[jk][1] = *(const uint32_t*)&Qs[r0 + 8 * ATS + kk + q * 2];
            qfr[jk][2] = *(const uint32_t*)&Qs[r0 + kk + 8 + q * 2];
            qfr[jk][3] = *(const uint32_t*)&Qs[r0 + 8 * ATS + kk + 8 + q * 2];
        }
    }

    float m0 = -1e30f, m1 = -1e30f, l0 = 0.f, l1 = 0.f;
    float O[8][4] = {};

    int ktmax = causal ? qt : (nkt - 1);
    for (int kt = 0; kt <= ktmax; kt++) {
        __syncthreads();
        #pragma unroll
        for (int i = 0; i < 4; i++) {
            int f = tid + 128 * i;
            int lr = f >> 3;
            int c8 = (f & 7) * 8;
            const __half* ks = Kb + (size_t)(rowbase + kt * 64 + lr) * DMODEL + colbase + c8;
            const __half* vs = Vb + (size_t)(rowbase + kt * 64 + lr) * DMODEL + colbase + c8;
            *(float4*)&Ks[lr * ATS + c8] = *(const float4*)ks;
            *(float4*)&Vs[lr * ATS + c8] = *(const float4*)vs;
        }
        __syncthreads();

        // S = Q @ K^T  (8 n-tiles of 8 keys)
        float S[8][4] = {};
        #pragma unroll
        for (int tn = 0; tn < 8; tn++) {
            #pragma unroll
            for (int jk = 0; jk < 4; jk++) {
                int n0 = (tn * 8 + g) * ATS + jk * 16 + q * 2;
                uint32_t b[2];
                b[0] = *(const uint32_t*)&Ks[n0];
                b[1] = *(const uint32_t*)&Ks[n0 + 8];
                mma_f16(S[tn], qfr[jk], b);
            }
        }

        // causal mask on diagonal tile
        if (causal && kt == qt) {
            int row0 = w * 16 + g;
            #pragma unroll
            for (int tn = 0; tn < 8; tn++) {
                int c0 = tn * 8 + q * 2;
                if (c0 > row0)           S[tn][0] = -1e30f;
                if (c0 + 1 > row0)       S[tn][1] = -1e30f;
                if (c0 > row0 + 8)       S[tn][2] = -1e30f;
                if (c0 + 1 > row0 + 8)   S[tn][3] = -1e30f;
            }
        }

        // row stats
        float rm0 = -1e30f, rm1 = -1e30f;
        #pragma unroll
        for (int tn = 0; tn < 8; tn++) {
            rm0 = fmaxf(rm0, fmaxf(S[tn][0], S[tn][1]));
            rm1 = fmaxf(rm1, fmaxf(S[tn][2], S[tn][3]));
        }
        #pragma unroll
        for (int o = 1; o <= 2; o <<= 1) {
            rm0 = fmaxf(rm0, __shfl_xor_sync(0xffffffffu, rm0, o));
            rm1 = fmaxf(rm1, __shfl_xor_sync(0xffffffffu, rm1, o));
        }
        float m0n = fmaxf(m0, rm0), m1n = fmaxf(m1, rm1);
        float al0 = __expf(m0 - m0n), al1 = __expf(m1 - m1n);
        float rs0 = 0.f, rs1 = 0.f;
        #pragma unroll
        for (int tn = 0; tn < 8; tn++) {
            S[tn][0] = __expf(S[tn][0] - m0n); rs0 += S[tn][0];
            S[tn][1] = __expf(S[tn][1] - m0n); rs0 += S[tn][1];
            S[tn][2] = __expf(S[tn][2] - m1n); rs1 += S[tn][2];
            S[tn][3] = __expf(S[tn][3] - m1n); rs1 += S[tn][3];
        }
        #pragma unroll
        for (int o = 1; o <= 2; o <<= 1) {
            rs0 += __shfl_xor_sync(0xffffffffu, rs0, o);
            rs1 += __shfl_xor_sync(0xffffffffu, rs1, o);
        }
        l0 = l0 * al0 + rs0; m0 = m0n;
        l1 = l1 * al1 + rs1; m1 = m1n;

        #pragma unroll
        for (int tn = 0; tn < 8; tn++) {
            O[tn][0] *= al0; O[tn][1] *= al0;
            O[tn][2] *= al1; O[tn][3] *= al1;
        }

        // O += P @ V
        #pragma unroll
        for (int jk = 0; jk < 4; jk++) {
            uint32_t a[4];
            a[0] = packh2(S[2 * jk][0],     S[2 * jk][1]);
            a[1] = packh2(S[2 * jk][2],     S[2 * jk][3]);
            a[2] = packh2(S[2 * jk + 1][0], S[2 * jk + 1][1]);
            a[3] = packh2(S[2 * jk + 1][2], S[2 * jk + 1][3]);
            int k0 = jk * 16 + q * 2;
            #pragma unroll
            for (int tn = 0; tn < 8; tn++) {
                int n = tn * 8 + g;
                uint32_t b[2];
                b[0] = packh2(__half2float(Vs[k0 * ATS + n]),
                              __half2float(Vs[(k0 + 1) * ATS + n]));
                b[1] = packh2(__half2float(Vs[(k0 + 8) * ATS + n]),
                              __half2float(Vs[(k0 + 9) * ATS + n]));
                mma_f16(O[tn], a, b);
            }
        }
    }

    // finalize
    float inv0 = 1.0f / l0, inv1 = 1.0f / l1;
    int row0 = rowbase + qt * 64 + w * 16 + g;
    #pragma unroll
    for (int tn = 0; tn < 8; tn++) {
        int col = colbase + tn * 8 + q * 2;
        *(uint32_t*)(Ctx + (size_t)row0 * DMODEL + col)       = packh2(O[tn][0] * inv0, O[tn][1] * inv0);
        *(uint32_t*)(Ctx + (size_t)(row0 + 8) * DMODEL + col) = packh2(O[tn][2] * inv1, O[tn][3] * inv1);
    }
}

// ---------------- driver -------------------------------------------------------
extern "C" void kernel_launch(void* const* d_in, const int* in_sizes, int n_in,
                              void* d_out, int out_size) {
    const float* tgt      = (const float*)d_in[0];
    const float* memory_f = (const float*)d_in[1];
    const float* self_wq  = (const float*)d_in[4];
    const float* self_bq  = (const float*)d_in[5];
    const float* self_wk  = (const float*)d_in[6];
    const float* self_bk  = (const float*)d_in[7];
    const float* self_wv  = (const float*)d_in[8];
    const float* self_bv  = (const float*)d_in[9];
    const float* self_wo  = (const float*)d_in[10];
    const float* self_bo  = (const float*)d_in[11];
    const float* cross_wq = (const float*)d_in[12];
    const float* cross_bq = (const float*)d_in[13];
    const float* cross_wk = (const float*)d_in[14];
    const float* cross_bk = (const float*)d_in[15];
    const float* cross_wv = (const float*)d_in[16];
    const float* cross_bv = (const float*)d_in[17];
    const float* cross_wo = (const float*)d_in[18];
    const float* cross_bo = (const float*)d_in[19];
    const float* ln1_g    = (const float*)d_in[20];
    const float* ln1_b    = (const float*)d_in[21];
    const float* ln2_g    = (const float*)d_in[22];
    const float* ln2_b    = (const float*)d_in[23];
    const float* ln3_g    = (const float*)d_in[24];
    const float* ln3_b    = (const float*)d_in[25];
    const float* ffn_w1   = (const float*)d_in[26];
    const float* ffn_b1   = (const float*)d_in[27];
    const float* ffn_w2   = (const float*)d_in[28];
    const float* ffn_b2   = (const float*)d_in[29];
    float* out = (float*)d_out;

    __half *ln, *q, *k, *v, *ctx, *ffn, *wh;
    float *x;
    cudaGetSymbolAddress((void**)&ln,  g_ln);
    cudaGetSymbolAddress((void**)&q,   g_q);
    cudaGetSymbolAddress((void**)&k,   g_k);
    cudaGetSymbolAddress((void**)&v,   g_v);
    cudaGetSymbolAddress((void**)&ctx, g_ctx);
    cudaGetSymbolAddress((void**)&x,   g_x);
    cudaGetSymbolAddress((void**)&ffn, g_ffn);
    cudaGetSymbolAddress((void**)&wh,  g_wh);

    const size_t M1 = 1024 * 1024;
    __half* t_swq = wh + 0 * M1;
    __half* t_swk = wh + 1 * M1;
    __half* t_swv = wh + 2 * M1;
    __half* t_swo = wh + 3 * M1;
    __half* t_cwq = wh + 4 * M1;
    __half* t_cwk = wh + 5 * M1;
    __half* t_cwv = wh + 6 * M1;
    __half* t_cwo = wh + 7 * M1;
    __half* t_w1  = wh + 8 * M1;    // [DFFN, DMODEL]
    __half* t_w2  = wh + 12 * M1;   // [DMODEL, DFFN]
    __half* mem_h = ln;             // reuse: half copy of memory (made before its use; ln rewritten later)

    dim3 blk(256);
    dim3 tb(32, 8);

    // ---- weight transposes+convert (Wt[n][k] = half(W[k][n])) ----
    transpose_cvt<<<dim3(32, 32),  tb>>>(self_wq,  t_swq, DMODEL, DMODEL);
    transpose_cvt<<<dim3(32, 32),  tb>>>(self_wk,  t_swk, DMODEL, DMODEL);
    transpose_cvt<<<dim3(32, 32),  tb>>>(self_wv,  t_swv, DMODEL, DMODEL);
    transpose_cvt<<<dim3(32, 32),  tb>>>(self_wo,  t_swo, DMODEL, DMODEL);
    transpose_cvt<<<dim3(32, 32),  tb>>>(cross_wq, t_cwq, DMODEL, DMODEL);
    transpose_cvt<<<dim3(32, 32),  tb>>>(cross_wk, t_cwk, DMODEL, DMODEL);
    transpose_cvt<<<dim3(32, 32),  tb>>>(cross_wv, t_cwv, DMODEL, DMODEL);
    transpose_cvt<<<dim3(32, 32),  tb>>>(cross_wo, t_cwo, DMODEL, DMODEL);
    transpose_cvt<<<dim3(128, 32), tb>>>(ffn_w1,   t_w1,  DMODEL, DFFN);
    transpose_cvt<<<dim3(32, 128), tb>>>(ffn_w2,   t_w2,  DFFN,   DMODEL);

    dim3 gD(DMODEL / BN, MROWS / BM);   // (8, 32)
    dim3 gF(DFFN / BN,   MROWS / BM);   // (32, 32)
    dim3 gA(LT / 64, B * NHEAD);

    // ---- sublayer 1: self-attention (pre-norm) ----
    ln_kernel<<<MROWS, blk>>>(tgt, ln1_g, ln1_b, ln);
    hgemm<true,  false, false><<<gD, blk>>>(ln, t_swq, self_bq, nullptr, q, MROWS, DMODEL, DMODEL);
    hgemm<true,  false, false><<<gD, blk>>>(ln, t_swk, self_bk, nullptr, k, MROWS, DMODEL, DMODEL);
    hgemm<true,  false, false><<<gD, blk>>>(ln, t_swv, self_bv, nullptr, v, MROWS, DMODEL, DMODEL);
    attn_kernel<<<gA, 128>>>(q, k, v, ctx, /*causal=*/1, LT / 64);
    hgemm<false, false, true ><<<gD, blk>>>(ctx, t_swo, self_bo, tgt, x, MROWS, DMODEL, DMODEL);

    // ---- sublayer 2: cross-attention ----
    // K/V from memory: need half LN-free input; project directly from fp32 memory.
    // Convert memory to half via LN-identity? No — memory enters raw. Use a
    // dedicated conversion: reuse ln buffer BEFORE ln2 overwrites it.
    // (memory -> mem_h)
    {
        // simple convert kernel inline: use transpose_cvt? No — write via ln path:
    }
    // conversion kernel launch (defined below via lambda-style global)
    extern __global__ void cvt_f2h(const float*, __half*, int);
    cvt_f2h<<<MROWS, 256>>>(memory_f, mem_h, DMODEL);
    hgemm<true,  false, false><<<gD, blk>>>(mem_h, t_cwk, cross_bk, nullptr, k, MROWS, DMODEL, DMODEL);
    hgemm<true,  false, false><<<gD, blk>>>(mem_h, t_cwv, cross_bv, nullptr, v, MROWS, DMODEL, DMODEL);
    ln_kernel<<<MROWS, blk>>>(x, ln2_g, ln2_b, ln);
    hgemm<true,  false, false><<<gD, blk>>>(ln, t_cwq, cross_bq, nullptr, q, MROWS, DMODEL, DMODEL);
    attn_kernel<<<gA, 128>>>(q, k, v, ctx, /*causal=*/0, LS / 64);
    hgemm<false, false, true ><<<gD, blk>>>(ctx, t_cwo, cross_bo, x, x, MROWS, DMODEL, DMODEL);

    // ---- sublayer 3: FFN ----
    ln_kernel<<<MROWS, blk>>>(x, ln3_g, ln3_b, ln);
    hgemm<true,  true,  false><<<gF, blk>>>(ln,  t_w1, ffn_b1, nullptr, ffn, MROWS, DFFN,   DMODEL);
    hgemm<false, false, true ><<<gD, blk>>>(ffn, t_w2, ffn_b2, x, out, MROWS, DMODEL, DFFN);
}

// fp32 -> fp16 row convert (256 threads, 4 elems each)
__global__ void cvt_f2h(const float* __restrict__ src, __half* __restrict__ dst, int ncol) {
    int row = blockIdx.x;
    int tid = threadIdx.x;
    float4 v = ((const float4*)(src + (size_t)row * ncol))[tid];
    uint2 o;
    o.x = packh2(v.x, v.y);
    o.y = packh2(v.z, v.w);
    ((uint2*)(dst + (size_t)row * ncol))[tid] = o;
}

// round 5
// speedup vs baseline: 6.9093x; 1.3093x over previous
#include <cuda_runtime.h>
#include <cuda_fp16.h>
#include <cstdint>
#include <math.h>

// Problem constants
#define B      4
#define LT     1024
#define LS     1024
#define DMODEL 1024
#define DFFN   4096
#define NHEAD  16
#define DKH    64
#define MROWS  (B * LT)   // 4096

// ---------------- scratch (static device allocations; no cudaMalloc) ----------
__device__ __half g_ln [MROWS * DMODEL];
__device__ __half g_q  [MROWS * DMODEL];
__device__ __half g_k  [MROWS * DMODEL];          // half copy of memory
__device__ __half g_ctx[MROWS * DMODEL];
__device__ float  g_x  [MROWS * DMODEL];
__device__ __half g_big[(size_t)MROWS * DFFN];    // qkv / ckv / ffn-hidden (aliased)
__device__ __half g_wh [16u * 1024u * 1024u];     // packed fp16 weights (native [K,N])
__device__ float  g_bias[5120];                   // packed qkv(3072) + ckv(2048) biases

// ================= helpers =====================================================
__device__ __forceinline__ uint32_t smem_u32(const void* p) {
    uint32_t a;
    asm("{ .reg .u64 t; cvta.to.shared.u64 t, %1; cvt.u32.u64 %0, t; }" : "=r"(a) : "l"(p));
    return a;
}
__device__ __forceinline__ uint32_t packh2(float a, float b) {
    __half2 h = __floats2half2_rn(a, b);
    return *(uint32_t*)&h;
}
__device__ __forceinline__ void mma_f16(float c[4], const uint32_t a[4], const uint32_t b[2]) {
    asm volatile(
        "mma.sync.aligned.m16n8k16.row.col.f32.f16.f16.f32 "
        "{%0,%1,%2,%3}, {%4,%5,%6,%7}, {%8,%9}, {%0,%1,%2,%3};"
        : "+f"(c[0]), "+f"(c[1]), "+f"(c[2]), "+f"(c[3])
        : "r"(a[0]), "r"(a[1]), "r"(a[2]), "r"(a[3]), "r"(b[0]), "r"(b[1]));
}
__device__ __forceinline__ void ldsm_x4(uint32_t r[4], uint32_t addr) {
    asm volatile("ldmatrix.sync.aligned.m8n8.x4.shared.b16 {%0,%1,%2,%3}, [%4];"
                 : "=r"(r[0]), "=r"(r[1]), "=r"(r[2]), "=r"(r[3]) : "r"(addr));
}
__device__ __forceinline__ void ldsm_x4_t(uint32_t r[4], uint32_t addr) {
    asm volatile("ldmatrix.sync.aligned.m8n8.x4.trans.shared.b16 {%0,%1,%2,%3}, [%4];"
                 : "=r"(r[0]), "=r"(r[1]), "=r"(r[2]), "=r"(r[3]) : "r"(addr));
}
__device__ __forceinline__ void cp16(uint32_t dst, const void* src) {
    asm volatile("cp.async.cg.shared.global [%0], [%1], 16;" :: "r"(dst), "l"(src) : "memory");
}
__device__ __forceinline__ void cp_commit() {
    asm volatile("cp.async.commit_group;" ::: "memory");
}
template<int N> __device__ __forceinline__ void cp_wait() {
    asm volatile("cp.async.wait_group %0;" :: "n"(N) : "memory");
}
__device__ __forceinline__ float gelu_tanh(float t) {
    return 0.5f * t * (1.0f + tanhf(0.7978845608028654f * (t + 0.044715f * t * t * t)));
}

// ---------------- weight convert + concat (no transpose) ----------------------
// g_wh half offsets (M1 = 1M): qkv 0, ckv 3M, cq 5M, so 6M, co 7M, f1 8M, f2 12M
__global__ void wcvt(const float* __restrict__ swq, const float* __restrict__ swk,
                     const float* __restrict__ swv, const float* __restrict__ swo,
                     const float* __restrict__ cwq, const float* __restrict__ cwk,
                     const float* __restrict__ cwv, const float* __restrict__ cwo,
                     const float* __restrict__ w1,  const float* __restrict__ w2,
                     __half* __restrict__ dst) {
    const size_t M1 = 1024 * 1024;
    size_t idx = ((size_t)blockIdx.x * 256 + threadIdx.x) * 8;
    const float* src;
    if (idx < 3 * M1) {
        size_t k = idx / 3072, n = idx % 3072;
        src = (n < 1024 ? swq : (n < 2048 ? swk : swv)) + k * 1024 + (n & 1023);
    } else if (idx < 5 * M1) {
        size_t r = idx - 3 * M1;
        size_t k = r / 2048, n = r % 2048;
        src = (n < 1024 ? cwk : cwv) + k * 1024 + (n & 1023);
    } else if (idx < 6 * M1)  src = cwq + (idx - 5 * M1);
    else if (idx < 7 * M1)    src = swo + (idx - 6 * M1);
    else if (idx < 8 * M1)    src = cwo + (idx - 7 * M1);
    else if (idx < 12 * M1)   src = w1  + (idx - 8 * M1);
    else                      src = w2  + (idx - 12 * M1);
    float4 v0 = *(const float4*)src;
    float4 v1 = *(const float4*)(src + 4);
    uint4 o;
    o.x = packh2(v0.x, v0.y); o.y = packh2(v0.z, v0.w);
    o.z = packh2(v1.x, v1.y); o.w = packh2(v1.z, v1.w);
    *(uint4*)(dst + idx) = o;
}

__global__ void bias_pack(const float* __restrict__ bq, const float* __restrict__ bk,
                          const float* __restrict__ bv, const float* __restrict__ cbk,
                          const float* __restrict__ cbv, float* __restrict__ dst) {
    int i = blockIdx.x * 256 + threadIdx.x;   // 0..5119
    float v;
    if (i < 1024)       v = bq[i];
    else if (i < 2048)  v = bk[i - 1024];
    else if (i < 3072)  v = bv[i - 2048];
    else if (i < 4096)  v = cbk[i - 3072];
    else                v = cbv[i - 4096];
    dst[i] = v;
}

// ---------------- LayerNorm: fp32 in, fp16 out --------------------------------
__global__ void ln_kernel(const float* __restrict__ x,
                          const float* __restrict__ g,
                          const float* __restrict__ b,
                          __half* __restrict__ y) {
    int row = blockIdx.x;
    const float4* xr = (const float4*)(x + (size_t)row * DMODEL);
    int tid = threadIdx.x;              // 256 threads, 4 floats each
    float4 xv = xr[tid];
    float s  = xv.x + xv.y + xv.z + xv.w;
    float ss = xv.x*xv.x + xv.y*xv.y + xv.z*xv.z + xv.w*xv.w;
    #pragma unroll
    for (int o = 16; o > 0; o >>= 1) {
        s  += __shfl_xor_sync(0xffffffffu, s, o);
        ss += __shfl_xor_sync(0xffffffffu, ss, o);
    }
    __shared__ float sh_s[8], sh_ss[8];
    int wid = tid >> 5, lane = tid & 31;
    if (lane == 0) { sh_s[wid] = s; sh_ss[wid] = ss; }
    __syncthreads();
    float ts = 0.f, tss = 0.f;
    #pragma unroll
    for (int w = 0; w < 8; w++) { ts += sh_s[w]; tss += sh_ss[w]; }
    float mean = ts * (1.0f / DMODEL);
    float var  = tss * (1.0f / DMODEL) - mean * mean;
    float rstd = rsqrtf(var + 1e-5f);
    float4 gv = ((const float4*)g)[tid];
    float4 bv = ((const float4*)b)[tid];
    uint2 o;
    o.x = packh2((xv.x - mean) * rstd * gv.x + bv.x, (xv.y - mean) * rstd * gv.y + bv.y);
    o.y = packh2((xv.z - mean) * rstd * gv.z + bv.z, (xv.w - mean) * rstd * gv.w + bv.w);
    ((uint2*)(y + (size_t)row * DMODEL))[tid] = o;
}

// fp32 -> fp16 row convert
__global__ void cvt_f2h(const float* __restrict__ src, __half* __restrict__ dst, int ncol) {
    int row = blockIdx.x;
    int tid = threadIdx.x;
    float4 v = ((const float4*)(src + (size_t)row * ncol))[tid];
    uint2 o;
    o.x = packh2(v.x, v.y);
    o.y = packh2(v.z, v.w);
    ((uint2*)(dst + (size_t)row * ncol))[tid] = o;
}

// ---------------- fp16 GEMM: cp.async 3-stage + ldmatrix ----------------------
// C[M,N] = A[M,K](half, lda=K) @ W[K,N](half, native k-major) (+bias)(+gelu)(+res fp32)
#define BM 128
#define BN 128
#define BK 32
#define SKH 40      // A smem row stride (halfs)
#define BNS 136     // B smem row stride (halfs)
#define ASTG 10240  // bytes per A stage (128*40*2)
#define BSTG 8704   // bytes per B stage (32*136*2)

template<bool OUT_HALF, bool GELU, bool RES>
__global__ __launch_bounds__(256)
void hgemm(const __half* __restrict__ A, const __half* __restrict__ W,
           const float* __restrict__ bias, const float* __restrict__ res,
           void* __restrict__ Cout, int M, int N, int K) {
    extern __shared__ char smem[];
    uint32_t as0 = smem_u32(smem);
    uint32_t bs0 = as0 + 3 * ASTG;

    int tid  = threadIdx.x;
    int wid  = tid >> 5;
    int lane = tid & 31;
    int g = lane >> 2, q = lane & 3;
    int rbase = (wid >> 2) * 64;
    int nbase = (wid & 3) * 32;

    int brow = blockIdx.y * BM;
    int bcol = blockIdx.x * BN;
    const int NKB = K / BK;

    int fa_r = tid >> 2;           // 0..63
    int fa_c = (tid & 3) * 8;
    int fb_r = tid >> 4;           // 0..15
    int fb_c = (tid & 15) * 8;

    auto issue = [&](int kb) {
        int s = kb % 3;
        const __half* Ag = A + (size_t)brow * K + (size_t)kb * BK;
        uint32_t ad = as0 + s * ASTG;
        #pragma unroll
        for (int i = 0; i < 2; i++) {
            int r = fa_r + 64 * i;
            cp16(ad + (r * SKH + fa_c) * 2, Ag + (size_t)r * K + fa_c);
        }
        const __half* Wg = W + (size_t)(kb * BK) * N + bcol;
        uint32_t bd = bs0 + s * BSTG;
        #pragma unroll
        for (int i = 0; i < 2; i++) {
            int r = fb_r + 16 * i;
            cp16(bd + (r * BNS + fb_c) * 2, Wg + (size_t)r * N + fb_c);
        }
        cp_commit();
    };

    // per-lane fragment offsets (in halfs)
    int a_off = (rbase + (lane & 15)) * SKH + ((lane >> 4) << 3);
    int b_off = (lane & 15) * BNS + nbase + ((lane >> 4) << 3);

    float acc[4][4][4] = {};

    issue(0);
    issue(1);
    cp_wait<1>();
    __syncthreads();

    for (int kb = 0; kb < NKB; kb++) {
        int s = kb % 3;
        uint32_t abase = as0 + s * ASTG;
        uint32_t bbase = bs0 + s * BSTG;
        #pragma unroll
        for (int kk = 0; kk < BK; kk += 16) {
            uint32_t af[4][4];
            #pragma unroll
            for (int tm = 0; tm < 4; tm++)
                ldsm_x4(af[tm], abase + (a_off + tm * 16 * SKH + kk) * 2);
            uint32_t bf[4][2];
            #pragma unroll
            for (int tp = 0; tp < 2; tp++) {
                uint32_t r4[4];
                ldsm_x4_t(r4, bbase + (b_off + kk * BNS + tp * 16) * 2);
                bf[2 * tp][0]     = r4[0]; bf[2 * tp][1]     = r4[1];
                bf[2 * tp + 1][0] = r4[2]; bf[2 * tp + 1][1] = r4[3];
            }
            #pragma unroll
            for (int tm = 0; tm < 4; tm++)
                #pragma unroll
                for (int tn = 0; tn < 4; tn++)
                    mma_f16(acc[tm][tn], af[tm], bf[tn]);
        }
        if (kb + 2 < NKB) issue(kb + 2); else cp_commit();
        cp_wait<1>();
        __syncthreads();
    }

    // ---- epilogue ----
    #pragma unroll
    for (int tm = 0; tm < 4; tm++) {
        #pragma unroll
        for (int half_i = 0; half_i < 2; half_i++) {
            int r = brow + rbase + tm * 16 + g + half_i * 8;
            #pragma unroll
            for (int tn = 0; tn < 4; tn++) {
                int c = bcol + nbase + tn * 8 + q * 2;
                float o0 = acc[tm][tn][half_i * 2 + 0] + bias[c];
                float o1 = acc[tm][tn][half_i * 2 + 1] + bias[c + 1];
                if (GELU) { o0 = gelu_tanh(o0); o1 = gelu_tanh(o1); }
                if (RES) {
                    float2 rv = *(const float2*)(res + (size_t)r * N + c);
                    o0 += rv.x; o1 += rv.y;
                }
                if (OUT_HALF) {
                    *(uint32_t*)((__half*)Cout + (size_t)r * N + c) = packh2(o0, o1);
                } else {
                    *(float2*)((float*)Cout + (size_t)r * N + c) = make_float2(o0, o1);
                }
            }
        }
    }
}
#define HGEMM_SMEM (3 * ASTG + 3 * BSTG)

// ---------------- fp16 flash attention: ldmatrix + cp.async double buffer -----
#define ATS 72
#define KTILE_B (64 * ATS * 2)
__global__ __launch_bounds__(128)
void attn_kernel(const __half* __restrict__ Qb, int qs,
                 const __half* __restrict__ Kb, int ks,
                 const __half* __restrict__ Vb, int vs,
                 __half* __restrict__ Ctx, int causal, int nkt) {
    __shared__ alignas(16) __half Qs[64 * ATS];
    __shared__ alignas(16) __half Ks[2][64 * ATS];
    __shared__ alignas(16) __half Vs[2][64 * ATS];

    int qt = blockIdx.x;
    int bh = blockIdx.y;
    int bb = bh >> 4, h = bh & 15;
    int rowbase = bb * LT;
    int colbase = h * DKH;
    int tid = threadIdx.x;
    int w = tid >> 5, lane = tid & 31;
    int g = lane >> 2, q = lane & 3;

    uint32_t ks_base = smem_u32(Ks);
    uint32_t vs_base = smem_u32(Vs);

    auto issue = [&](int kt) {
        int s = kt & 1;
        const __half* kg = Kb + (size_t)(rowbase + kt * 64) * ks + colbase;
        const __half* vg = Vb + (size_t)(rowbase + kt * 64) * vs + colbase;
        #pragma unroll
        for (int i = 0; i < 4; i++) {
            int f = tid + 128 * i;
            int r = f >> 3;
            int c8 = (f & 7) * 8;
            cp16(ks_base + s * KTILE_B + (r * ATS + c8) * 2, kg + (size_t)r * ks + c8);
            cp16(vs_base + s * KTILE_B + (r * ATS + c8) * 2, vg + (size_t)r * vs + c8);
        }
        cp_commit();
    };

    issue(0);

    // load Q tile (scaled by 1/8)
    {
        const __half2 sc = __floats2half2_rn(0.125f, 0.125f);
        #pragma unroll
        for (int i = 0; i < 4; i++) {
            int f = tid + 128 * i;
            int lr = f >> 3;
            int c8 = (f & 7) * 8;
            const __half2* src = (const __half2*)(Qb + (size_t)(rowbase + qt * 64 + lr) * qs + colbase + c8);
            __half2 vv[4];
            #pragma unroll
            for (int j = 0; j < 4; j++) vv[j] = __hmul2(src[j], sc);
            *(float4*)&Qs[lr * ATS + c8] = *(float4*)vv;
        }
    }
    __syncthreads();

    // Q fragments
    uint32_t qfr[4][4];
    {
        int r0 = (w * 16 + g) * ATS;
        #pragma unroll
        for (int jk = 0; jk < 4; jk++) {
            int kk = jk * 16;
            qfr[jk][0] = *(const uint32_t*)&Qs[r0 + kk + q * 2];
            qfr[jk][1] = *(const uint32_t*)&Qs[r0 + 8 * ATS + kk + q * 2];
            qfr[jk][2] = *(const uint32_t*)&Qs[r0 + kk + 8 + q * 2];
            qfr[jk][3] = *(const uint32_t*)&Qs[r0 + 8 * ATS + kk + 8 + q * 2];
        }
    }

    // per-lane ldmatrix offsets (halfs)
    int kq_off = (((lane >> 4) << 3) + (lane & 7)) * ATS + (((lane >> 3) & 1) << 3);
    int vv_off = lane * ATS;

    float m0 = -1e30f, m1 = -1e30f, l0 = 0.f, l1 = 0.f;
    float O[8][4] = {};

    int ktmax = causal ? qt : (nkt - 1);
    for (int kt = 0; kt <= ktmax; kt++) {
        if (kt + 1 <= ktmax) { issue(kt + 1); cp_wait<1>(); }
        else                 { cp_commit();   cp_wait<1>(); }
        __syncthreads();
        int s = kt & 1;
        uint32_t kb_s = ks_base + s * KTILE_B;
        uint32_t vb_s = vs_base + s * KTILE_B;

        // S = Q @ K^T
        float S[8][4] = {};
        #pragma unroll
        for (int jk = 0; jk < 4; jk++) {
            #pragma unroll
            for (int tp = 0; tp < 4; tp++) {
                uint32_t r4[4];
                ldsm_x4(r4, kb_s + (kq_off + tp * 16 * ATS + jk * 16) * 2);
                uint32_t bA[2] = { r4[0], r4[1] };
                uint32_t bB[2] = { r4[2], r4[3] };
                mma_f16(S[2 * tp],     qfr[jk], bA);
                mma_f16(S[2 * tp + 1], qfr[jk], bB);
            }
        }

        // causal mask on diagonal tile
        if (causal && kt == qt) {
            int row0 = w * 16 + g;
            #pragma unroll
            for (int tn = 0; tn < 8; tn++) {
                int c0 = tn * 8 + q * 2;
                if (c0 > row0)         S[tn][0] = -1e30f;
                if (c0 + 1 > row0)     S[tn][1] = -1e30f;
                if (c0 > row0 + 8)     S[tn][2] = -1e30f;
                if (c0 + 1 > row0 + 8) S[tn][3] = -1e30f;
            }
        }

        // online softmax
        float rm0 = -1e30f, rm1 = -1e30f;
        #pragma unroll
        for (int tn = 0; tn < 8; tn++) {
            rm0 = fmaxf(rm0, fmaxf(S[tn][0], S[tn][1]));
            rm1 = fmaxf(rm1, fmaxf(S[tn][2], S[tn][3]));
        }
        #pragma unroll
        for (int o = 1; o <= 2; o <<= 1) {
            rm0 = fmaxf(rm0, __shfl_xor_sync(0xffffffffu, rm0, o));
            rm1 = fmaxf(rm1, __shfl_xor_sync(0xffffffffu, rm1, o));
        }
        float m0n = fmaxf(m0, rm0), m1n = fmaxf(m1, rm1);
        float al0 = __expf(m0 - m0n), al1 = __expf(m1 - m1n);
        float rs0 = 0.f, rs1 = 0.f;
        #pragma unroll
        for (int tn = 0; tn < 8; tn++) {
            S[tn][0] = __expf(S[tn][0] - m0n); rs0 += S[tn][0];
            S[tn][1] = __expf(S[tn][1] - m0n); rs0 += S[tn][1];
            S[tn][2] = __expf(S[tn][2] - m1n); rs1 += S[tn][2];
            S[tn][3] = __expf(S[tn][3] - m1n); rs1 += S[tn][3];
        }
        #pragma unroll
        for (int o = 1; o <= 2; o <<= 1) {
            rs0 += __shfl_xor_sync(0xffffffffu, rs0, o);
            rs1 += __shfl_xor_sync(0xffffffffu, rs1, o);
        }
        l0 = l0 * al0 + rs0; m0 = m0n;
        l1 = l1 * al1 + rs1; m1 = m1n;

        #pragma unroll
        for (int tn = 0; tn < 8; tn++) {
            O[tn][0] *= al0; O[tn][1] *= al0;
            O[tn][2] *= al1; O[tn][3] *= al1;
        }

        // P fragments
        uint32_t ap[4][4];
        #pragma unroll
        for (int jk = 0; jk < 4; jk++) {
            ap[jk][0] = packh2(S[2 * jk][0],     S[2 * jk][1]);
            ap[jk][1] = packh2(S[2 * jk][2],     S[2 * jk][3]);
            ap[jk][2] = packh2(S[2 * jk + 1][0], S[2 * jk + 1][1]);
            ap[jk][3] = packh2(S[2 * jk + 1][2], S[2 * jk + 1][3]);
        }

        // O += P @ V (V^T fragments via ldmatrix.trans)
        #pragma unroll
        for (int tn = 0; tn < 8; tn++) {
            #pragma unroll
            for (int j2 = 0; j2 < 2; j2++) {
                uint32_t r4[4];
                ldsm_x4_t(r4, vb_s + (j2 * 32 * ATS + vv_off + tn * 8) * 2);
                uint32_t bA[2] = { r4[0], r4[1] };
                uint32_t bB[2] = { r4[2], r4[3] };
                mma_f16(O[tn], ap[2 * j2],     bA);
                mma_f16(O[tn], ap[2 * j2 + 1], bB);
            }
        }
        __syncthreads();
    }

    // finalize
    float inv0 = 1.0f / l0, inv1 = 1.0f / l1;
    int row0 = rowbase + qt * 64 + w * 16 + g;
    #pragma unroll
    for (int tn = 0; tn < 8; tn++) {
        int col = colbase + tn * 8 + q * 2;
        *(uint32_t*)(Ctx + (size_t)row0 * DMODEL + col)       = packh2(O[tn][0] * inv0, O[tn][1] * inv0);
        *(uint32_t*)(Ctx + (size_t)(row0 + 8) * DMODEL + col) = packh2(O[tn][2] * inv1, O[tn][3] * inv1);
    }
}

// ---------------- driver -------------------------------------------------------
extern "C" void kernel_launch(void* const* d_in, const int* in_sizes, int n_in,
                              void* d_out, int out_size) {
    const float* tgt      = (const float*)d_in[0];
    const float* memory_f = (const float*)d_in[1];
    const float* self_wq  = (const float*)d_in[4];
    const float* self_bq  = (const float*)d_in[5];
    const float* self_wk  = (const float*)d_in[6];
    const float* self_bk  = (const float*)d_in[7];
    const float* self_wv  = (const float*)d_in[8];
    const float* self_bv  = (const float*)d_in[9];
    const float* self_wo  = (const float*)d_in[10];
    const float* self_bo  = (const float*)d_in[11];
    const float* cross_wq = (const float*)d_in[12];
    const float* cross_bq = (const float*)d_in[13];
    const float* cross_wk = (const float*)d_in[14];
    const float* cross_bk = (const float*)d_in[15];
    const float* cross_wv = (const float*)d_in[16];
    const float* cross_bv = (const float*)d_in[17];
    const float* cross_wo = (const float*)d_in[18];
    const float* cross_bo = (const float*)d_in[19];
    const float* ln1_g    = (const float*)d_in[20];
    const float* ln1_b    = (const float*)d_in[21];
    const float* ln2_g    = (const float*)d_in[22];
    const float* ln2_b    = (const float*)d_in[23];
    const float* ln3_g    = (const float*)d_in[24];
    const float* ln3_b    = (const float*)d_in[25];
    const float* ffn_w1   = (const float*)d_in[26];
    const float* ffn_b1   = (const float*)d_in[27];
    const float* ffn_w2   = (const float*)d_in[28];
    const float* ffn_b2   = (const float*)d_in[29];
    float* out = (float*)d_out;

    __half *ln, *cq, *memh, *ctx, *big, *wh;
    float *x, *bias;
    cudaGetSymbolAddress((void**)&ln,   g_ln);
    cudaGetSymbolAddress((void**)&cq,   g_q);
    cudaGetSymbolAddress((void**)&memh, g_k);
    cudaGetSymbolAddress((void**)&ctx,  g_ctx);
    cudaGetSymbolAddress((void**)&x,    g_x);
    cudaGetSymbolAddress((void**)&big,  g_big);
    cudaGetSymbolAddress((void**)&wh,   g_wh);
    cudaGetSymbolAddress((void**)&bias, g_bias);

    const size_t M1 = 1024 * 1024;
    __half* w_qkv = wh + 0;
    __half* w_ckv = wh + 3 * M1;
    __half* w_cq  = wh + 5 * M1;
    __half* w_so  = wh + 6 * M1;
    __half* w_co  = wh + 7 * M1;
    __half* w_f1  = wh + 8 * M1;
    __half* w_f2  = wh + 12 * M1;
    float* b_qkv = bias;
    float* b_ckv = bias + 3072;

    cudaFuncSetAttribute(hgemm<true,  false, false>, cudaFuncAttributeMaxDynamicSharedMemorySize, HGEMM_SMEM);
    cudaFuncSetAttribute(hgemm<false, false, true >, cudaFuncAttributeMaxDynamicSharedMemorySize, HGEMM_SMEM);
    cudaFuncSetAttribute(hgemm<true,  true,  false>, cudaFuncAttributeMaxDynamicSharedMemorySize, HGEMM_SMEM);

    dim3 blk(256);
    dim3 gQKV(3072 / BN, MROWS / BM);   // (24, 32)
    dim3 gCKV(2048 / BN, MROWS / BM);   // (16, 32)
    dim3 gD(DMODEL / BN, MROWS / BM);   // (8, 32)
    dim3 gF(DFFN / BN,   MROWS / BM);   // (32, 32)
    dim3 gA(LT / 64, B * NHEAD);        // (16, 64)

    // ---- preprocessing ----
    wcvt<<<8192, blk>>>(self_wq, self_wk, self_wv, self_wo,
                        cross_wq, cross_wk, cross_wv, cross_wo, ffn_w1, ffn_w2, wh);
    bias_pack<<<20, blk>>>(self_bq, self_bk, self_bv, cross_bk, cross_bv, bias);
    cvt_f2h<<<MROWS, blk>>>(memory_f, memh, DMODEL);

    // ---- sublayer 1: self-attention (pre-norm) ----
    ln_kernel<<<MROWS, blk>>>(tgt, ln1_g, ln1_b, ln);
    hgemm<true,  false, false><<<gQKV, blk, HGEMM_SMEM>>>(ln, w_qkv, b_qkv, nullptr, big, MROWS, 3072, DMODEL);
    attn_kernel<<<gA, 128>>>(big, 3072, big + 1024, 3072, big + 2048, 3072, ctx, /*causal=*/1, LT / 64);
    hgemm<false, false, true ><<<gD, blk, HGEMM_SMEM>>>(ctx, w_so, self_bo, tgt, x, MROWS, DMODEL, DMODEL);

    // ---- sublayer 2: cross-attention ----
    hgemm<true,  false, false><<<gCKV, blk, HGEMM_SMEM>>>(memh, w_ckv, b_ckv, nullptr, big, MROWS, 2048, DMODEL);
    ln_kernel<<<MROWS, blk>>>(x, ln2_g, ln2_b, ln);
    hgemm<true,  false, false><<<gD, blk, HGEMM_SMEM>>>(ln, w_cq, cross_bq, nullptr, cq, MROWS, DMODEL, DMODEL);
    attn_kernel<<<gA, 128>>>(cq, 1024, big, 2048, big + 1024, 2048, ctx, /*causal=*/0, LS / 64);
    hgemm<false, false, true ><<<gD, blk, HGEMM_SMEM>>>(ctx, w_co, cross_bo, x, x, MROWS, DMODEL, DMODEL);

    // ---- sublayer 3: FFN ----
    ln_kernel<<<MROWS, blk>>>(x, ln3_g, ln3_b, ln);
    hgemm<true,  true,  false><<<gF, blk, HGEMM_SMEM>>>(ln, w_f1, ffn_b1, nullptr, big, MROWS, DFFN, DMODEL);
    hgemm<false, false, true ><<<gD, blk, HGEMM_SMEM>>>(big, w_f2, ffn_b2, x, out, MROWS, DMODEL, DFFN);
}

// round 6
// speedup vs baseline: 7.3335x; 1.0614x over previous
#include <cuda_runtime.h>
#include <cuda_fp16.h>
#include <cstdint>
#include <math.h>

// Problem constants
#define B      4
#define LT     1024
#define LS     1024
#define DMODEL 1024
#define DFFN   4096
#define NHEAD  16
#define DKH    64
#define MROWS  (B * LT)   // 4096

// ---------------- scratch (static device allocations; no cudaMalloc) ----------
__device__ __half g_ln [MROWS * DMODEL];
__device__ __half g_q  [MROWS * DMODEL];
__device__ __half g_k  [MROWS * DMODEL];          // half copy of memory
__device__ __half g_ctx[MROWS * DMODEL];
__device__ float  g_x  [MROWS * DMODEL];
__device__ __half g_big[(size_t)MROWS * DFFN];    // qkv / ckv / ffn-hidden (aliased)
__device__ __half g_wh [16u * 1024u * 1024u];     // packed fp16 weights (native [K,N])
__device__ float  g_bias[5120];                   // packed qkv(3072) + ckv(2048) biases

// ================= helpers =====================================================
__device__ __forceinline__ uint32_t smem_u32(const void* p) {
    uint32_t a;
    asm("{ .reg .u64 t; cvta.to.shared.u64 t, %1; cvt.u32.u64 %0, t; }" : "=r"(a) : "l"(p));
    return a;
}
__device__ __forceinline__ uint32_t packh2(float a, float b) {
    __half2 h = __floats2half2_rn(a, b);
    return *(uint32_t*)&h;
}
__device__ __forceinline__ void mma_f16(float c[4], const uint32_t a[4], const uint32_t b[2]) {
    asm volatile(
        "mma.sync.aligned.m16n8k16.row.col.f32.f16.f16.f32 "
        "{%0,%1,%2,%3}, {%4,%5,%6,%7}, {%8,%9}, {%0,%1,%2,%3};"
        : "+f"(c[0]), "+f"(c[1]), "+f"(c[2]), "+f"(c[3])
        : "r"(a[0]), "r"(a[1]), "r"(a[2]), "r"(a[3]), "r"(b[0]), "r"(b[1]));
}
__device__ __forceinline__ void ldsm_x4(uint32_t r[4], uint32_t addr) {
    asm volatile("ldmatrix.sync.aligned.m8n8.x4.shared.b16 {%0,%1,%2,%3}, [%4];"
                 : "=r"(r[0]), "=r"(r[1]), "=r"(r[2]), "=r"(r[3]) : "r"(addr));
}
__device__ __forceinline__ void ldsm_x4_t(uint32_t r[4], uint32_t addr) {
    asm volatile("ldmatrix.sync.aligned.m8n8.x4.trans.shared.b16 {%0,%1,%2,%3}, [%4];"
                 : "=r"(r[0]), "=r"(r[1]), "=r"(r[2]), "=r"(r[3]) : "r"(addr));
}
__device__ __forceinline__ void cp16(uint32_t dst, const void* src) {
    asm volatile("cp.async.cg.shared.global [%0], [%1], 16;" :: "r"(dst), "l"(src) : "memory");
}
__device__ __forceinline__ void cp_commit() {
    asm volatile("cp.async.commit_group;" ::: "memory");
}
template<int N> __device__ __forceinline__ void cp_wait() {
    asm volatile("cp.async.wait_group %0;" :: "n"(N) : "memory");
}
__device__ __forceinline__ float gelu_tanh(float t) {
    return 0.5f * t * (1.0f + tanhf(0.7978845608028654f * (t + 0.044715f * t * t * t)));
}

// ---------------- weight convert + concat (no transpose) ----------------------
// g_wh half offsets (M1 = 1M): qkv 0, ckv 3M, cq 5M, so 6M, co 7M, f1 8M, f2 12M
__global__ void wcvt(const float* __restrict__ swq, const float* __restrict__ swk,
                     const float* __restrict__ swv, const float* __restrict__ swo,
                     const float* __restrict__ cwq, const float* __restrict__ cwk,
                     const float* __restrict__ cwv, const float* __restrict__ cwo,
                     const float* __restrict__ w1,  const float* __restrict__ w2,
                     __half* __restrict__ dst) {
    const size_t M1 = 1024 * 1024;
    size_t idx = ((size_t)blockIdx.x * 256 + threadIdx.x) * 8;
    const float* src;
    if (idx < 3 * M1) {
        size_t k = idx / 3072, n = idx % 3072;
        src = (n < 1024 ? swq : (n < 2048 ? swk : swv)) + k * 1024 + (n & 1023);
    } else if (idx < 5 * M1) {
        size_t r = idx - 3 * M1;
        size_t k = r / 2048, n = r % 2048;
        src = (n < 1024 ? cwk : cwv) + k * 1024 + (n & 1023);
    } else if (idx < 6 * M1)  src = cwq + (idx - 5 * M1);
    else if (idx < 7 * M1)    src = swo + (idx - 6 * M1);
    else if (idx < 8 * M1)    src = cwo + (idx - 7 * M1);
    else if (idx < 12 * M1)   src = w1  + (idx - 8 * M1);
    else                      src = w2  + (idx - 12 * M1);
    float4 v0 = *(const float4*)src;
    float4 v1 = *(const float4*)(src + 4);
    uint4 o;
    o.x = packh2(v0.x, v0.y); o.y = packh2(v0.z, v0.w);
    o.z = packh2(v1.x, v1.y); o.w = packh2(v1.z, v1.w);
    *(uint4*)(dst + idx) = o;
}

__global__ void bias_pack(const float* __restrict__ bq, const float* __restrict__ bk,
                          const float* __restrict__ bv, const float* __restrict__ cbk,
                          const float* __restrict__ cbv, float* __restrict__ dst) {
    int i = blockIdx.x * 256 + threadIdx.x;   // 0..5119
    float v;
    if (i < 1024)       v = bq[i];
    else if (i < 2048)  v = bk[i - 1024];
    else if (i < 3072)  v = bv[i - 2048];
    else if (i < 4096)  v = cbk[i - 3072];
    else                v = cbv[i - 4096];
    dst[i] = v;
}

// ---------------- LayerNorm: fp32 in, fp16 out --------------------------------
__global__ void ln_kernel(const float* __restrict__ x,
                          const float* __restrict__ g,
                          const float* __restrict__ b,
                          __half* __restrict__ y) {
    int row = blockIdx.x;
    const float4* xr = (const float4*)(x + (size_t)row * DMODEL);
    int tid = threadIdx.x;              // 256 threads, 4 floats each
    float4 xv = xr[tid];
    float s  = xv.x + xv.y + xv.z + xv.w;
    float ss = xv.x*xv.x + xv.y*xv.y + xv.z*xv.z + xv.w*xv.w;
    #pragma unroll
    for (int o = 16; o > 0; o >>= 1) {
        s  += __shfl_xor_sync(0xffffffffu, s, o);
        ss += __shfl_xor_sync(0xffffffffu, ss, o);
    }
    __shared__ float sh_s[8], sh_ss[8];
    int wid = tid >> 5, lane = tid & 31;
    if (lane == 0) { sh_s[wid] = s; sh_ss[wid] = ss; }
    __syncthreads();
    float ts = 0.f, tss = 0.f;
    #pragma unroll
    for (int w = 0; w < 8; w++) { ts += sh_s[w]; tss += sh_ss[w]; }
    float mean = ts * (1.0f / DMODEL);
    float var  = tss * (1.0f / DMODEL) - mean * mean;
    float rstd = rsqrtf(var + 1e-5f);
    float4 gv = ((const float4*)g)[tid];
    float4 bv = ((const float4*)b)[tid];
    uint2 o;
    o.x = packh2((xv.x - mean) * rstd * gv.x + bv.x, (xv.y - mean) * rstd * gv.y + bv.y);
    o.y = packh2((xv.z - mean) * rstd * gv.z + bv.z, (xv.w - mean) * rstd * gv.w + bv.w);
    ((uint2*)(y + (size_t)row * DMODEL))[tid] = o;
}

// fp32 -> fp16 row convert
__global__ void cvt_f2h(const float* __restrict__ src, __half* __restrict__ dst, int ncol) {
    int row = blockIdx.x;
    int tid = threadIdx.x;
    float4 v = ((const float4*)(src + (size_t)row * ncol))[tid];
    uint2 o;
    o.x = packh2(v.x, v.y);
    o.y = packh2(v.z, v.w);
    ((uint2*)(dst + (size_t)row * ncol))[tid] = o;
}

// ---------------- fp16 GEMM: cp.async 3-stage + ldmatrix, 2 CTAs/SM ----------
// C[M,N] = A[M,K](half, lda=K) @ W[K,N](half, native k-major) (+bias)(+gelu)(+res fp32)
#define BM 128
#define BN 128
#define BK 32
#define SKH 40      // A smem row stride (halfs)
#define BNS 136     // B smem row stride (halfs)
#define ASTG 10240  // bytes per A stage (128*40*2)
#define BSTG 8704   // bytes per B stage (32*136*2)

template<bool OUT_HALF, bool GELU, bool RES>
__global__ __launch_bounds__(256, 2)
void hgemm(const __half* __restrict__ A, const __half* __restrict__ W,
           const float* __restrict__ bias, const float* __restrict__ res,
           void* __restrict__ Cout, int M, int N, int K) {
    extern __shared__ char smem[];
    uint32_t as0 = smem_u32(smem);
    uint32_t bs0 = as0 + 3 * ASTG;

    int tid  = threadIdx.x;
    int wid  = tid >> 5;
    int lane = tid & 31;
    int g = lane >> 2, q = lane & 3;
    int rbase = (wid >> 2) * 64;
    int nbase = (wid & 3) * 32;

    int brow = blockIdx.y * BM;
    int bcol = blockIdx.x * BN;
    const int NKB = K / BK;

    int fa_r = tid >> 2;           // 0..63
    int fa_c = (tid & 3) * 8;
    int fb_r = tid >> 4;           // 0..15
    int fb_c = (tid & 15) * 8;

    auto issue = [&](int kb) {
        int s = kb % 3;
        const __half* Ag = A + (size_t)brow * K + (size_t)kb * BK;
        uint32_t ad = as0 + s * ASTG;
        #pragma unroll
        for (int i = 0; i < 2; i++) {
            int r = fa_r + 64 * i;
            cp16(ad + (r * SKH + fa_c) * 2, Ag + (size_t)r * K + fa_c);
        }
        const __half* Wg = W + (size_t)(kb * BK) * N + bcol;
        uint32_t bd = bs0 + s * BSTG;
        #pragma unroll
        for (int i = 0; i < 2; i++) {
            int r = fb_r + 16 * i;
            cp16(bd + (r * BNS + fb_c) * 2, Wg + (size_t)r * N + fb_c);
        }
        cp_commit();
    };

    // per-lane fragment offsets (in halfs)
    int a_off = (rbase + (lane & 15)) * SKH + ((lane >> 4) << 3);
    int b_off = (lane & 15) * BNS + nbase + ((lane >> 4) << 3);

    float acc[4][4][4] = {};

    issue(0);
    issue(1);
    cp_wait<1>();
    __syncthreads();

    for (int kb = 0; kb < NKB; kb++) {
        int s = kb % 3;
        uint32_t abase = as0 + s * ASTG;
        uint32_t bbase = bs0 + s * BSTG;
        #pragma unroll
        for (int kk = 0; kk < BK; kk += 16) {
            uint32_t af[4][4];
            #pragma unroll
            for (int tm = 0; tm < 4; tm++)
                ldsm_x4(af[tm], abase + (a_off + tm * 16 * SKH + kk) * 2);
            uint32_t bf[4][2];
            #pragma unroll
            for (int tp = 0; tp < 2; tp++) {
                uint32_t r4[4];
                ldsm_x4_t(r4, bbase + (b_off + kk * BNS + tp * 16) * 2);
                bf[2 * tp][0]     = r4[0]; bf[2 * tp][1]     = r4[1];
                bf[2 * tp + 1][0] = r4[2]; bf[2 * tp + 1][1] = r4[3];
            }
            #pragma unroll
            for (int tm = 0; tm < 4; tm++)
                #pragma unroll
                for (int tn = 0; tn < 4; tn++)
                    mma_f16(acc[tm][tn], af[tm], bf[tn]);
        }
        if (kb + 2 < NKB) {
            issue(kb + 2);
            cp_wait<1>();
            __syncthreads();
        } else if (kb + 1 < NKB) {
            cp_wait<0>();
            __syncthreads();
        }
    }

    // ---- epilogue ----
    #pragma unroll
    for (int tm = 0; tm < 4; tm++) {
        #pragma unroll
        for (int half_i = 0; half_i < 2; half_i++) {
            int r = brow + rbase + tm * 16 + g + half_i * 8;
            #pragma unroll
            for (int tn = 0; tn < 4; tn++) {
                int c = bcol + nbase + tn * 8 + q * 2;
                float o0 = acc[tm][tn][half_i * 2 + 0] + bias[c];
                float o1 = acc[tm][tn][half_i * 2 + 1] + bias[c + 1];
                if (GELU) { o0 = gelu_tanh(o0); o1 = gelu_tanh(o1); }
                if (RES) {
                    float2 rv = *(const float2*)(res + (size_t)r * N + c);
                    o0 += rv.x; o1 += rv.y;
                }
                if (OUT_HALF) {
                    *(uint32_t*)((__half*)Cout + (size_t)r * N + c) = packh2(o0, o1);
                } else {
                    *(float2*)((float*)Cout + (size_t)r * N + c) = make_float2(o0, o1);
                }
            }
        }
    }
}
#define HGEMM_SMEM (3 * ASTG + 3 * BSTG)

// ---------------- fp16 flash attention: ldmatrix + cp.async double buffer -----
#define ATS 72
#define KTILE_B (64 * ATS * 2)
__global__ __launch_bounds__(128)
void attn_kernel(const __half* __restrict__ Qb, int qs,
                 const __half* __restrict__ Kb, int ks,
                 const __half* __restrict__ Vb, int vs,
                 __half* __restrict__ Ctx, int causal, int nkt) {
    __shared__ alignas(16) __half Qs[64 * ATS];
    __shared__ alignas(16) __half Ks[2][64 * ATS];
    __shared__ alignas(16) __half Vs[2][64 * ATS];

    int qt = blockIdx.x;
    int bh = blockIdx.y;
    int bb = bh >> 4, h = bh & 15;
    int rowbase = bb * LT;
    int colbase = h * DKH;
    int tid = threadIdx.x;
    int w = tid >> 5, lane = tid & 31;
    int g = lane >> 2, q = lane & 3;

    uint32_t ks_base = smem_u32(Ks);
    uint32_t vs_base = smem_u32(Vs);

    auto issue = [&](int kt) {
        int s = kt & 1;
        const __half* kg = Kb + (size_t)(rowbase + kt * 64) * ks + colbase;
        const __half* vg = Vb + (size_t)(rowbase + kt * 64) * vs + colbase;
        #pragma unroll
        for (int i = 0; i < 4; i++) {
            int f = tid + 128 * i;
            int r = f >> 3;
            int c8 = (f & 7) * 8;
            cp16(ks_base + s * KTILE_B + (r * ATS + c8) * 2, kg + (size_t)r * ks + c8);
            cp16(vs_base + s * KTILE_B + (r * ATS + c8) * 2, vg + (size_t)r * vs + c8);
        }
        cp_commit();
    };

    issue(0);

    // load Q tile (scaled by 1/8)
    {
        const __half2 sc = __floats2half2_rn(0.125f, 0.125f);
        #pragma unroll
        for (int i = 0; i < 4; i++) {
            int f = tid + 128 * i;
            int lr = f >> 3;
            int c8 = (f & 7) * 8;
            const __half2* src = (const __half2*)(Qb + (size_t)(rowbase + qt * 64 + lr) * qs + colbase + c8);
            __half2 vv[4];
            #pragma unroll
            for (int j = 0; j < 4; j++) vv[j] = __hmul2(src[j], sc);
            *(float4*)&Qs[lr * ATS + c8] = *(float4*)vv;
        }
    }
    __syncthreads();

    // Q fragments
    uint32_t qfr[4][4];
    {
        int r0 = (w * 16 + g) * ATS;
        #pragma unroll
        for (int jk = 0; jk < 4; jk++) {
            int kk = jk * 16;
            qfr[jk][0] = *(const uint32_t*)&Qs[r0 + kk + q * 2];
            qfr[jk][1] = *(const uint32_t*)&Qs[r0 + 8 * ATS + kk + q * 2];
            qfr[jk][2] = *(const uint32_t*)&Qs[r0 + kk + 8 + q * 2];
            qfr[jk][3] = *(const uint32_t*)&Qs[r0 + 8 * ATS + kk + 8 + q * 2];
        }
    }

    // per-lane ldmatrix offsets (halfs)
    int kq_off = (((lane >> 4) << 3) + (lane & 7)) * ATS + (((lane >> 3) & 1) << 3);
    int vv_off = lane * ATS;

    float m0 = -1e30f, m1 = -1e30f, l0 = 0.f, l1 = 0.f;
    float O[8][4] = {};

    int ktmax = causal ? qt : (nkt - 1);
    for (int kt = 0; kt <= ktmax; kt++) {
        if (kt + 1 <= ktmax) { issue(kt + 1); cp_wait<1>(); }
        else                 { cp_wait<0>(); }
        __syncthreads();
        int s = kt & 1;
        uint32_t kb_s = ks_base + s * KTILE_B;
        uint32_t vb_s = vs_base + s * KTILE_B;

        // S = Q @ K^T
        float S[8][4] = {};
        #pragma unroll
        for (int jk = 0; jk < 4; jk++) {
            #pragma unroll
            for (int tp = 0; tp < 4; tp++) {
                uint32_t r4[4];
                ldsm_x4(r4, kb_s + (kq_off + tp * 16 * ATS + jk * 16) * 2);
                uint32_t bA[2] = { r4[0], r4[1] };
                uint32_t bB[2] = { r4[2], r4[3] };
                mma_f16(S[2 * tp],     qfr[jk], bA);
                mma_f16(S[2 * tp + 1], qfr[jk], bB);
            }
        }

        // causal mask on diagonal tile
        if (causal && kt == qt) {
            int row0 = w * 16 + g;
            #pragma unroll
            for (int tn = 0; tn < 8; tn++) {
                int c0 = tn * 8 + q * 2;
                if (c0 > row0)         S[tn][0] = -1e30f;
                if (c0 + 1 > row0)     S[tn][1] = -1e30f;
                if (c0 > row0 + 8)     S[tn][2] = -1e30f;
                if (c0 + 1 > row0 + 8) S[tn][3] = -1e30f;
            }
        }

        // online softmax
        float rm0 = -1e30f, rm1 = -1e30f;
        #pragma unroll
        for (int tn = 0; tn < 8; tn++) {
            rm0 = fmaxf(rm0, fmaxf(S[tn][0], S[tn][1]));
            rm1 = fmaxf(rm1, fmaxf(S[tn][2], S[tn][3]));
        }
        #pragma unroll
        for (int o = 1; o <= 2; o <<= 1) {
            rm0 = fmaxf(rm0, __shfl_xor_sync(0xffffffffu, rm0, o));
            rm1 = fmaxf(rm1, __shfl_xor_sync(0xffffffffu, rm1, o));
        }
        float m0n = fmaxf(m0, rm0), m1n = fmaxf(m1, rm1);
        float al0 = __expf(m0 - m0n), al1 = __expf(m1 - m1n);
        float rs0 = 0.f, rs1 = 0.f;
        #pragma unroll
        for (int tn = 0; tn < 8; tn++) {
            S[tn][0] = __expf(S[tn][0] - m0n); rs0 += S[tn][0];
            S[tn][1] = __expf(S[tn][1] - m0n); rs0 += S[tn][1];
            S[tn][2] = __expf(S[tn][2] - m1n); rs1 += S[tn][2];
            S[tn][3] = __expf(S[tn][3] - m1n); rs1 += S[tn][3];
        }
        #pragma unroll
        for (int o = 1; o <= 2; o <<= 1) {
            rs0 += __shfl_xor_sync(0xffffffffu, rs0, o);
            rs1 += __shfl_xor_sync(0xffffffffu, rs1, o);
        }
        l0 = l0 * al0 + rs0; m0 = m0n;
        l1 = l1 * al1 + rs1; m1 = m1n;

        #pragma unroll
        for (int tn = 0; tn < 8; tn++) {
            O[tn][0] *= al0; O[tn][1] *= al0;
            O[tn][2] *= al1; O[tn][3] *= al1;
        }

        // P fragments
        uint32_t ap[4][4];
        #pragma unroll
        for (int jk = 0; jk < 4; jk++) {
            ap[jk][0] = packh2(S[2 * jk][0],     S[2 * jk][1]);
            ap[jk][1] = packh2(S[2 * jk][2],     S[2 * jk][3]);
            ap[jk][2] = packh2(S[2 * jk + 1][0], S[2 * jk + 1][1]);
            ap[jk][3] = packh2(S[2 * jk + 1][2], S[2 * jk + 1][3]);
        }

        // O += P @ V (V^T fragments via ldmatrix.trans)
        #pragma unroll
        for (int tn = 0; tn < 8; tn++) {
            #pragma unroll
            for (int j2 = 0; j2 < 2; j2++) {
                uint32_t r4[4];
                ldsm_x4_t(r4, vb_s + (j2 * 32 * ATS + vv_off + tn * 8) * 2);
                uint32_t bA[2] = { r4[0], r4[1] };
                uint32_t bB[2] = { r4[2], r4[3] };
                mma_f16(O[tn], ap[2 * j2],     bA);
                mma_f16(O[tn], ap[2 * j2 + 1], bB);
            }
        }
        __syncthreads();
    }

    // finalize
    float inv0 = 1.0f / l0, inv1 = 1.0f / l1;
    int row0 = rowbase + qt * 64 + w * 16 + g;
    #pragma unroll
    for (int tn = 0; tn < 8; tn++) {
        int col = colbase + tn * 8 + q * 2;
        *(uint32_t*)(Ctx + (size_t)row0 * DMODEL + col)       = packh2(O[tn][0] * inv0, O[tn][1] * inv0);
        *(uint32_t*)(Ctx + (size_t)(row0 + 8) * DMODEL + col) = packh2(O[tn][2] * inv1, O[tn][3] * inv1);
    }
}

// ---------------- driver -------------------------------------------------------
extern "C" void kernel_launch(void* const* d_in, const int* in_sizes, int n_in,
                              void* d_out, int out_size) {
    const float* tgt      = (const float*)d_in[0];
    const float* memory_f = (const float*)d_in[1];
    const float* self_wq  = (const float*)d_in[4];
    const float* self_bq  = (const float*)d_in[5];
    const float* self_wk  = (const float*)d_in[6];
    const float* self_bk  = (const float*)d_in[7];
    const float* self_wv  = (const float*)d_in[8];
    const float* self_bv  = (const float*)d_in[9];
    const float* self_wo  = (const float*)d_in[10];
    const float* self_bo  = (const float*)d_in[11];
    const float* cross_wq = (const float*)d_in[12];
    const float* cross_bq = (const float*)d_in[13];
    const float* cross_wk = (const float*)d_in[14];
    const float* cross_bk = (const float*)d_in[15];
    const float* cross_wv = (const float*)d_in[16];
    const float* cross_bv = (const float*)d_in[17];
    const float* cross_wo = (const float*)d_in[18];
    const float* cross_bo = (const float*)d_in[19];
    const float* ln1_g    = (const float*)d_in[20];
    const float* ln1_b    = (const float*)d_in[21];
    const float* ln2_g    = (const float*)d_in[22];
    const float* ln2_b    = (const float*)d_in[23];
    const float* ln3_g    = (const float*)d_in[24];
    const float* ln3_b    = (const float*)d_in[25];
    const float* ffn_w1   = (const float*)d_in[26];
    const float* ffn_b1   = (const float*)d_in[27];
    const float* ffn_w2   = (const float*)d_in[28];
    const float* ffn_b2   = (const float*)d_in[29];
    float* out = (float*)d_out;

    __half *ln, *cq, *memh, *ctx, *big, *wh;
    float *x, *bias;
    cudaGetSymbolAddress((void**)&ln,   g_ln);
    cudaGetSymbolAddress((void**)&cq,   g_q);
    cudaGetSymbolAddress((void**)&memh, g_k);
    cudaGetSymbolAddress((void**)&ctx,  g_ctx);
    cudaGetSymbolAddress((void**)&x,    g_x);
    cudaGetSymbolAddress((void**)&big,  g_big);
    cudaGetSymbolAddress((void**)&wh,   g_wh);
    cudaGetSymbolAddress((void**)&bias, g_bias);

    const size_t M1 = 1024 * 1024;
    __half* w_qkv = wh + 0;
    __half* w_ckv = wh + 3 * M1;
    __half* w_cq  = wh + 5 * M1;
    __half* w_so  = wh + 6 * M1;
    __half* w_co  = wh + 7 * M1;
    __half* w_f1  = wh + 8 * M1;
    __half* w_f2  = wh + 12 * M1;
    float* b_qkv = bias;
    float* b_ckv = bias + 3072;

    cudaFuncSetAttribute(hgemm<true,  false, false>, cudaFuncAttributeMaxDynamicSharedMemorySize, HGEMM_SMEM);
    cudaFuncSetAttribute(hgemm<false, false, true >, cudaFuncAttributeMaxDynamicSharedMemorySize, HGEMM_SMEM);
    cudaFuncSetAttribute(hgemm<true,  true,  false>, cudaFuncAttributeMaxDynamicSharedMemorySize, HGEMM_SMEM);

    dim3 blk(256);
    dim3 gQKV(3072 / BN, MROWS / BM);   // (24, 32)
    dim3 gCKV(2048 / BN, MROWS / BM);   // (16, 32)
    dim3 gD(DMODEL / BN, MROWS / BM);   // (8, 32)
    dim3 gF(DFFN / BN,   MROWS / BM);   // (32, 32)
    dim3 gA(LT / 64, B * NHEAD);        // (16, 64)

    // ---- preprocessing ----
    wcvt<<<8192, blk>>>(self_wq, self_wk, self_wv, self_wo,
                        cross_wq, cross_wk, cross_wv, cross_wo, ffn_w1, ffn_w2, wh);
    bias_pack<<<20, blk>>>(self_bq, self_bk, self_bv, cross_bk, cross_bv, bias);
    cvt_f2h<<<MROWS, blk>>>(memory_f, memh, DMODEL);

    // ---- sublayer 1: self-attention (pre-norm) ----
    ln_kernel<<<MROWS, blk>>>(tgt, ln1_g, ln1_b, ln);
    hgemm<true,  false, false><<<gQKV, blk, HGEMM_SMEM>>>(ln, w_qkv, b_qkv, nullptr, big, MROWS, 3072, DMODEL);
    attn_kernel<<<gA, 128>>>(big, 3072, big + 1024, 3072, big + 2048, 3072, ctx, /*causal=*/1, LT / 64);
    hgemm<false, false, true ><<<gD, blk, HGEMM_SMEM>>>(ctx, w_so, self_bo, tgt, x, MROWS, DMODEL, DMODEL);

    // ---- sublayer 2: cross-attention ----
    hgemm<true,  false, false><<<gCKV, blk, HGEMM_SMEM>>>(memh, w_ckv, b_ckv, nullptr, big, MROWS, 2048, DMODEL);
    ln_kernel<<<MROWS, blk>>>(x, ln2_g, ln2_b, ln);
    hgemm<true,  false, false><<<gD, blk, HGEMM_SMEM>>>(ln, w_cq, cross_bq, nullptr, cq, MROWS, DMODEL, DMODEL);
    attn_kernel<<<gA, 128>>>(cq, 1024, big, 2048, big + 1024, 2048, ctx, /*causal=*/0, LS / 64);
    hgemm<false, false, true ><<<gD, blk, HGEMM_SMEM>>>(ctx, w_co, cross_bo, x, x, MROWS, DMODEL, DMODEL);

    // ---- sublayer 3: FFN ----
    ln_kernel<<<MROWS, blk>>>(x, ln3_g, ln3_b, ln);
    hgemm<true,  true,  false><<<gF, blk, HGEMM_SMEM>>>(ln, w_f1, ffn_b1, nullptr, big, MROWS, DFFN, DMODEL);
    hgemm<false, false, true ><<<gD, blk, HGEMM_SMEM>>>(big, w_f2, ffn_b2, x, out, MROWS, DMODEL, DFFN);
}